// round 1
// baseline (speedup 1.0000x reference)
#include <cuda_runtime.h>

// ---------------- problem constants ----------------
#define NB      128
#define SEQ     77
#define DMODEL  1024
#define NHEAD   16
#define DHEAD   64
#define FF      4096
#define NEXP    8
#define TOPK    2
#define TOK     (NB * SEQ)          // 9856
#define QKVD    (3 * DMODEL)        // 3072

// ---------------- scratch (device globals; no allocation) ----------------
__device__ float g_xn  [(size_t)TOK * DMODEL];
__device__ float g_qkv [(size_t)TOK * QKVD];
__device__ float g_ao  [(size_t)TOK * DMODEL];
__device__ float g_x   [(size_t)TOK * DMODEL];
__device__ float g_ffn [(size_t)TOK * DMODEL];
__device__ float g_hmoe[(size_t)NB * TOPK * SEQ * FF];     // 80.7M floats
__device__ float g_eo  [(size_t)NB * TOPK * SEQ * DMODEL]; // 20.2M floats
__device__ float g_hsh [(size_t)TOK * FF];                 // 40.4M floats
__device__ float g_sho [(size_t)TOK * DMODEL];
__device__ int   g_topi [NB * TOPK];
__device__ float g_gates[NB * TOPK];

// ---------------- layernorm ----------------
__global__ __launch_bounds__(256) void ln_kernel(
    const float* __restrict__ x, const float* __restrict__ w,
    const float* __restrict__ bvec, float* __restrict__ y)
{
    long t = blockIdx.x;
    const float* xr = x + t * DMODEL;
    float* yr = y + t * DMODEL;
    int tid = threadIdx.x;
    float v[4];
    float s = 0.f, s2 = 0.f;
#pragma unroll
    for (int i = 0; i < 4; i++) {
        v[i] = xr[tid + i * 256];
        s += v[i]; s2 += v[i] * v[i];
    }
#pragma unroll
    for (int o = 16; o; o >>= 1) {
        s  += __shfl_xor_sync(0xffffffffu, s, o);
        s2 += __shfl_xor_sync(0xffffffffu, s2, o);
    }
    __shared__ float rs[8], rs2[8];
    if ((tid & 31) == 0) { rs[tid >> 5] = s; rs2[tid >> 5] = s2; }
    __syncthreads();
    float ts = 0.f, ts2 = 0.f;
#pragma unroll
    for (int i = 0; i < 8; i++) { ts += rs[i]; ts2 += rs2[i]; }
    float mean = ts * (1.0f / DMODEL);
    float var  = ts2 * (1.0f / DMODEL) - mean * mean;
    float inv  = rsqrtf(var + 1e-5f);
#pragma unroll
    for (int i = 0; i < 4; i++) {
        int d = tid + i * 256;
        yr[d] = (v[i] - mean) * inv * w[d] + bvec[d];
    }
}

// ---------------- generic tiled SGEMM ----------------
// C[z] = epilogue( A[z/aDiv] @ op(B[widx]) + bias[widx] (+ resid) )
// BT=false: B row-major [K,N] (C = A@B).  BT=true: B row-major [N,K] (C = A@B^T).
// widx = expertIdx ? expertIdx[z] : z.
template<bool BT, bool RELU>
__global__ __launch_bounds__(256) void gemm_kernel(
    const float* __restrict__ A, const float* __restrict__ Bm,
    const float* __restrict__ bias, const float* __restrict__ resid,
    float* __restrict__ C, int M, int N, int K,
    long sA, int aDiv, long sB, long sBias, long sC,
    const int* __restrict__ eIdx)
{
    __shared__ __align__(16) float As[16][68];
    __shared__ __align__(16) float Bs[16][68];

    int z = blockIdx.z;
    int widx = eIdx ? eIdx[z] : z;
    const float* Ap = A + (long)(z / aDiv) * sA;
    const float* Bp = Bm + (long)widx * sB;
    const float* biasp = bias ? (bias + (long)widx * sBias) : nullptr;
    float* Cp = C + (long)z * sC;

    int m0 = blockIdx.y * 64;
    int n0 = blockIdx.x * 64;
    int tid = threadIdx.x;
    int tx = tid & 15, ty = tid >> 4;

    int am  = tid >> 2;            // 0..63 row within tile
    int ak4 = (tid & 3) * 4;       // 0,4,8,12
    int bk  = tid >> 4;            // 0..15 (TN load)
    int bn4 = (tid & 15) * 4;

    float acc[4][4] = {};

    for (int k0 = 0; k0 < K; k0 += 16) {
        // A tile -> As[k][m]  (transposed)
        float4 av = make_float4(0.f, 0.f, 0.f, 0.f);
        if (m0 + am < M)
            av = *(const float4*)(Ap + (long)(m0 + am) * K + k0 + ak4);
        As[ak4 + 0][am] = av.x; As[ak4 + 1][am] = av.y;
        As[ak4 + 2][am] = av.z; As[ak4 + 3][am] = av.w;

        if (!BT) {
            float4 bv = *(const float4*)(Bp + (long)(k0 + bk) * N + n0 + bn4);
            *(float4*)&Bs[bk][bn4] = bv;
        } else {
            float4 bv = *(const float4*)(Bp + (long)(n0 + am) * K + k0 + ak4);
            Bs[ak4 + 0][am] = bv.x; Bs[ak4 + 1][am] = bv.y;
            Bs[ak4 + 2][am] = bv.z; Bs[ak4 + 3][am] = bv.w;
        }
        __syncthreads();

#pragma unroll
        for (int kk = 0; kk < 16; kk++) {
            float4 a4 = *(const float4*)&As[kk][ty * 4];
            float4 b4 = *(const float4*)&Bs[kk][tx * 4];
            float a[4] = {a4.x, a4.y, a4.z, a4.w};
            float b[4] = {b4.x, b4.y, b4.z, b4.w};
#pragma unroll
            for (int i = 0; i < 4; i++)
#pragma unroll
                for (int j = 0; j < 4; j++)
                    acc[i][j] += a[i] * b[j];
        }
        __syncthreads();
    }

#pragma unroll
    for (int i = 0; i < 4; i++) {
        int row = m0 + ty * 4 + i;
        if (row >= M) break;
        long rowoff = (long)row * N;
#pragma unroll
        for (int j = 0; j < 4; j++) {
            int col = n0 + tx * 4 + j;
            float v = acc[i][j];
            if (biasp) v += biasp[col];
            if (RELU)  v = fmaxf(v, 0.f);
            if (resid) v += resid[rowoff + col];
            Cp[rowoff + col] = v;
        }
    }
}

// ---------------- fused attention (one block per (b,h)) ----------------
__global__ __launch_bounds__(256) void attn_kernel(
    const float* __restrict__ qkv, float* __restrict__ ao)
{
    __shared__ float Ks[SEQ * 65];
    __shared__ float Vs[SEQ * 65];
    __shared__ float qb[8][64];
    __shared__ float pb[8][80];

    int bh = blockIdx.x;
    int b = bh >> 4, h = bh & 15;
    int tid = threadIdx.x, lane = tid & 31, wrp = tid >> 5;
    long tok0 = (long)b * SEQ;

    for (int idx = tid; idx < SEQ * 64; idx += 256) {
        int s = idx >> 6, d = idx & 63;
        long off = (tok0 + s) * QKVD + h * 64 + d;
        Ks[s * 65 + d] = qkv[off + DMODEL];
        Vs[s * 65 + d] = qkv[off + 2 * DMODEL];
    }
    __syncthreads();

    for (int s = wrp; s < SEQ; s += 8) {
        long qoff = (tok0 + s) * QKVD + h * 64;
        qb[wrp][lane]      = qkv[qoff + lane];
        qb[wrp][lane + 32] = qkv[qoff + lane + 32];
        __syncwarp();

        float e[3];
        float mx = -1e30f;
#pragma unroll
        for (int jj = 0; jj < 3; jj++) {
            int j = lane + jj * 32;
            float dot = -1e30f;
            if (j < SEQ) {
                const float* kr = Ks + j * 65;
                float a = 0.f;
#pragma unroll
                for (int d = 0; d < 64; d++) a += qb[wrp][d] * kr[d];
                dot = a * 0.125f;   // 1/sqrt(64)
            }
            e[jj] = dot;
            mx = fmaxf(mx, dot);
        }
#pragma unroll
        for (int o = 16; o; o >>= 1) mx = fmaxf(mx, __shfl_xor_sync(0xffffffffu, mx, o));

        float ssum = 0.f;
#pragma unroll
        for (int jj = 0; jj < 3; jj++) {
            int j = lane + jj * 32;
            float p = (j < SEQ) ? __expf(e[jj] - mx) : 0.f;
            e[jj] = p; ssum += p;
        }
#pragma unroll
        for (int o = 16; o; o >>= 1) ssum += __shfl_xor_sync(0xffffffffu, ssum, o);
        float inv = 1.0f / ssum;
#pragma unroll
        for (int jj = 0; jj < 3; jj++) {
            int j = lane + jj * 32;
            if (j < SEQ) pb[wrp][j] = e[jj] * inv;
        }
        __syncwarp();

        float a0 = 0.f, a1 = 0.f;
        for (int j = 0; j < SEQ; j++) {
            float p = pb[wrp][j];
            a0 += p * Vs[j * 65 + lane];
            a1 += p * Vs[j * 65 + lane + 32];
        }
        long orow = (tok0 + s) * DMODEL + h * 64;
        ao[orow + lane]      = a0;
        ao[orow + lane + 32] = a1;
        __syncwarp();
    }
}

// ---------------- router: logits(token0) -> top-2 + softmax gates ----------------
__global__ __launch_bounds__(256) void router_kernel(
    const float* __restrict__ ffn, const float* __restrict__ rw,
    int* __restrict__ topi, float* __restrict__ gates)
{
    int b = blockIdx.x;
    const float* xr = ffn + (long)b * SEQ * DMODEL;   // token 0 of sequence b
    int tid = threadIdx.x;
    int e = tid >> 5, lane = tid & 31;
    const float* wr = rw + e * DMODEL;
    float s = 0.f;
    for (int d = lane; d < DMODEL; d += 32) s += xr[d] * wr[d];
#pragma unroll
    for (int o = 16; o; o >>= 1) s += __shfl_xor_sync(0xffffffffu, s, o);
    __shared__ float lg[NEXP];
    if (lane == 0) lg[e] = s;
    __syncthreads();
    if (tid == 0) {
        int i0 = 0; float v0 = lg[0];
        for (int i = 1; i < NEXP; i++) if (lg[i] > v0) { v0 = lg[i]; i0 = i; }
        int i1 = -1; float v1 = -1e30f;
        for (int i = 0; i < NEXP; i++) if (i != i0 && lg[i] > v1) { v1 = lg[i]; i1 = i; }
        float e1 = __expf(v1 - v0);
        float den = 1.f + e1;
        topi[b * TOPK]     = i0;
        topi[b * TOPK + 1] = i1;
        gates[b * TOPK]     = 1.f / den;
        gates[b * TOPK + 1] = e1 / den;
    }
}

// ---------------- final combine: x + shared + g0*eo0 + g1*eo1 ----------------
__global__ __launch_bounds__(256) void combine_kernel(
    const float* __restrict__ x, const float* __restrict__ sho,
    const float* __restrict__ eo, const float* __restrict__ gates,
    float* __restrict__ out)
{
    long t = blockIdx.x;
    int tid = threadIdx.x;
    int b = (int)(t / SEQ);
    int s = (int)(t - (long)b * SEQ);
    float g0 = gates[b * TOPK], g1 = gates[b * TOPK + 1];
    long base = t * DMODEL;
    long e0 = ((long)(b * TOPK) * SEQ + s) * DMODEL;
    long e1 = e0 + (long)SEQ * DMODEL;
#pragma unroll
    for (int i = 0; i < 4; i++) {
        int d = tid + i * 256;
        out[base + d] = x[base + d] + sho[base + d] + g0 * eo[e0 + d] + g1 * eo[e1 + d];
    }
}

// ---------------- launch ----------------
extern "C" void kernel_launch(void* const* d_in, const int* in_sizes, int n_in,
                              void* d_out, int out_size)
{
    const float* src   = (const float*)d_in[0];
    const float* pw    = (const float*)d_in[1];
    const float* pbias = (const float*)d_in[2];
    const float* ow    = (const float*)d_in[3];
    const float* ob    = (const float*)d_in[4];
    const float* ln1w  = (const float*)d_in[5];
    const float* ln1b  = (const float*)d_in[6];
    const float* ln2w  = (const float*)d_in[7];
    const float* ln2b  = (const float*)d_in[8];
    const float* rw    = (const float*)d_in[9];
    const float* ew1   = (const float*)d_in[10];
    const float* eb1   = (const float*)d_in[11];
    const float* ew2   = (const float*)d_in[12];
    const float* eb2   = (const float*)d_in[13];
    const float* sw1   = (const float*)d_in[14];
    const float* sb1   = (const float*)d_in[15];
    const float* sw2   = (const float*)d_in[16];
    const float* sb2   = (const float*)d_in[17];

    float *xn, *qkv, *ao, *x, *ffn, *hmoe, *eo, *hsh, *sho, *gates;
    int *topi;
    cudaGetSymbolAddress((void**)&xn,   g_xn);
    cudaGetSymbolAddress((void**)&qkv,  g_qkv);
    cudaGetSymbolAddress((void**)&ao,   g_ao);
    cudaGetSymbolAddress((void**)&x,    g_x);
    cudaGetSymbolAddress((void**)&ffn,  g_ffn);
    cudaGetSymbolAddress((void**)&hmoe, g_hmoe);
    cudaGetSymbolAddress((void**)&eo,   g_eo);
    cudaGetSymbolAddress((void**)&hsh,  g_hsh);
    cudaGetSymbolAddress((void**)&sho,  g_sho);
    cudaGetSymbolAddress((void**)&topi, g_topi);
    cudaGetSymbolAddress((void**)&gates,g_gates);

    const int mt_tok = (TOK + 63) / 64;  // 154
    const int mt_seq = (SEQ + 63) / 64;  // 2

    // 1. LN1
    ln_kernel<<<TOK, 256>>>(src, ln1w, ln1b, xn);
    // 2. QKV = xn @ packed_w^T + packed_b
    gemm_kernel<true, false><<<dim3(QKVD / 64, mt_tok, 1), 256>>>(
        xn, pw, pbias, nullptr, qkv, TOK, QKVD, DMODEL, 0, 1, 0, 0, 0, nullptr);
    // 3. attention
    attn_kernel<<<NB * NHEAD, 256>>>(qkv, ao);
    // 4. x = src + ao @ out_w^T + out_b
    gemm_kernel<true, false><<<dim3(DMODEL / 64, mt_tok, 1), 256>>>(
        ao, ow, ob, src, x, TOK, DMODEL, DMODEL, 0, 1, 0, 0, 0, nullptr);
    // 5. LN2
    ln_kernel<<<TOK, 256>>>(x, ln2w, ln2b, ffn);
    // 6. router top-2
    router_kernel<<<NB, 256>>>(ffn, rw, topi, gates);
    // 7. MoE layer 1: h = relu(ffn[b] @ ew1[e] + eb1[e])     [per (b,k)]
    gemm_kernel<false, true><<<dim3(FF / 64, mt_seq, NB * TOPK), 256>>>(
        ffn, ew1, eb1, nullptr, hmoe, SEQ, FF, DMODEL,
        (long)SEQ * DMODEL, TOPK, (long)DMODEL * FF, FF, (long)SEQ * FF, topi);
    // 8. MoE layer 2: eo = h @ ew2[e] + eb2[e]
    gemm_kernel<false, false><<<dim3(DMODEL / 64, mt_seq, NB * TOPK), 256>>>(
        hmoe, ew2, eb2, nullptr, eo, SEQ, DMODEL, FF,
        (long)SEQ * FF, 1, (long)FF * DMODEL, DMODEL, (long)SEQ * DMODEL, topi);
    // 9. shared expert layer 1: hsh = relu(ffn @ sw1 + sb1)
    gemm_kernel<false, true><<<dim3(FF / 64, mt_tok, 1), 256>>>(
        ffn, sw1, sb1, nullptr, hsh, TOK, FF, DMODEL, 0, 1, 0, 0, 0, nullptr);
    // 10. shared expert layer 2: sho = hsh @ sw2 + sb2
    gemm_kernel<false, false><<<dim3(DMODEL / 64, mt_tok, 1), 256>>>(
        hsh, sw2, sb2, nullptr, sho, TOK, DMODEL, FF, 0, 1, 0, 0, 0, nullptr);
    // 11. out = x + moe + shared
    combine_kernel<<<TOK, 256>>>(x, sho, eo, gates, (float*)d_out);
}

// round 3
// speedup vs baseline: 3.8435x; 3.8435x over previous
#include <cuda_runtime.h>

// ---------------- problem constants ----------------
#define NB      128
#define SEQ     77
#define DMODEL  1024
#define NHEAD   16
#define FF      4096
#define NEXP    8
#define TOPK    2
#define TOK     (NB * SEQ)          // 9856
#define QKVD    (3 * DMODEL)        // 3072

// ---------------- scratch (device globals; no allocation) ----------------
__device__ float g_xn  [(size_t)TOK * DMODEL];
__device__ float g_qkv [(size_t)TOK * QKVD];
__device__ float g_ao  [(size_t)TOK * DMODEL];
__device__ float g_x   [(size_t)TOK * DMODEL];
__device__ float g_ffn [(size_t)TOK * DMODEL];
__device__ float g_hmoe[(size_t)NB * TOPK * SEQ * FF];
__device__ float g_eo  [(size_t)NB * TOPK * SEQ * DMODEL];
__device__ float g_hsh [(size_t)TOK * FF];
__device__ float g_sho [(size_t)TOK * DMODEL];
__device__ int   g_topi [NB * TOPK];
__device__ float g_gates[NB * TOPK];

// ---------------- helpers ----------------
__device__ __forceinline__ unsigned cvt_tf32(float x) {
    unsigned r;
    asm("cvt.rna.tf32.f32 %0, %1;" : "=r"(r) : "f"(x));
    return r;
}
__device__ __forceinline__ void cp_async16(void* dst, const void* src, int sz) {
    unsigned saddr = (unsigned)__cvta_generic_to_shared(dst);
    asm volatile("cp.async.cg.shared.global [%0], [%1], 16, %2;\n"
                 :: "r"(saddr), "l"(src), "r"(sz));
}
__device__ __forceinline__ void cp_commit() {
    asm volatile("cp.async.commit_group;\n");
}
__device__ __forceinline__ void cp_wait1() {
    asm volatile("cp.async.wait_group 1;\n");
}

// smem tile geometry (floats)
#define ASTRIDE   36        // [m][k] / [n][k] pad: bank = 4m+k -> conflict-free
#define BSTRIDE_NN 136      // [k][n]  pad: bank = 8k+n  -> conflict-free
#define ABUF (128 * ASTRIDE)            // 4608 floats per buffer
#define BBUF 4608                       // max(128*36, 32*136)
#define SMEM_FLOATS (2 * ABUF + 2 * BBUF)
#define SMEM_BYTES  (SMEM_FLOATS * 4)   // 73728

// ---------------- TF32 tensor-core GEMM ----------------
// C[z] = epi( A[z/aDiv] @ op(B[widx]) + bias[widx] (+resid) )
// BT=false: B row-major [K,N].  BT=true: B row-major [N,K] (C = A@B^T).
template<bool BT, bool RELU>
__global__ void __launch_bounds__(256, 2) tgemm(
    const float* __restrict__ A, const float* __restrict__ Bm,
    const float* __restrict__ bias, const float* __restrict__ resid,
    float* __restrict__ C, int M, int N, int K,
    long sA, int aDiv, long sB, long sBias, long sC,
    const int* __restrict__ eIdx)
{
    extern __shared__ float sm[];
    float* As = sm;             // two buffers of ABUF
    float* Bs = sm + 2 * ABUF;  // two buffers of BBUF

    int z = blockIdx.z;
    int widx = eIdx ? eIdx[z] : z;
    const float* Ap = A + (long)(z / aDiv) * sA;
    const float* Bp = Bm + (long)widx * sB;
    const float* biasp = bias ? (bias + (long)widx * sBias) : nullptr;
    float* Cp = C + (long)z * sC;

    int m0 = blockIdx.y * 128;
    int n0 = blockIdx.x * 128;
    int tid = threadIdx.x, lane = tid & 31, w = tid >> 5;
    int warp_m = (w & 3) * 32;
    int warp_n = (w >> 2) * 64;

    float c[2][8][4];
#pragma unroll
    for (int i = 0; i < 2; i++)
#pragma unroll
        for (int j = 0; j < 8; j++)
#pragma unroll
            for (int q = 0; q < 4; q++) c[i][j][q] = 0.f;

    const int nChunks = K >> 5;

    // -------- async copy of one 32-wide K chunk --------
    auto copyA = [&](int k0, int buf) {
        float* dst = As + buf * ABUF;
#pragma unroll
        for (int i = 0; i < 4; i++) {
            int f = tid + i * 256;
            int row = f >> 3;            // 0..127
            int kq  = (f & 7) * 4;       // 0..28
            int gr = m0 + row;
            int sz = (gr < M) ? 16 : 0;
            const float* src = Ap + (long)(gr < M ? gr : M - 1) * K + k0 + kq;
            cp_async16(dst + row * ASTRIDE + kq, src, sz);
        }
    };
    auto copyB = [&](int k0, int buf) {
        float* dst = Bs + buf * BBUF;
        if (BT) {
#pragma unroll
            for (int i = 0; i < 4; i++) {
                int f = tid + i * 256;
                int row = f >> 3;        // n within tile (N % 128 == 0 always)
                int kq  = (f & 7) * 4;
                const float* src = Bp + (long)(n0 + row) * K + k0 + kq;
                cp_async16(dst + row * ASTRIDE + kq, src, 16);
            }
        } else {
#pragma unroll
            for (int i = 0; i < 4; i++) {
                int f = tid + i * 256;
                int krow = f >> 5;       // 0..31
                int nq   = (f & 31) * 4; // 0..124
                const float* src = Bp + (long)(k0 + krow) * N + n0 + nq;
                cp_async16(dst + krow * BSTRIDE_NN + nq, src, 16);
            }
        }
    };

    copyA(0, 0); copyB(0, 0);
    cp_commit();

    for (int ch = 0; ch < nChunks; ch++) {
        if (ch + 1 < nChunks) {
            copyA((ch + 1) << 5, (ch + 1) & 1);
            copyB((ch + 1) << 5, (ch + 1) & 1);
        }
        cp_commit();          // empty group on last iter keeps wait math uniform
        cp_wait1();
        __syncthreads();

        const float* Ab = As + (ch & 1) * ABUF;
        const float* Bb = Bs + (ch & 1) * BBUF;

#pragma unroll
        for (int kk = 0; kk < 32; kk += 8) {
            unsigned a[2][4];
#pragma unroll
            for (int mi = 0; mi < 2; mi++) {
                int r  = warp_m + mi * 16 + (lane >> 2);
                int kb = kk + (lane & 3);
                a[mi][0] = cvt_tf32(Ab[r * ASTRIDE + kb]);
                a[mi][1] = cvt_tf32(Ab[(r + 8) * ASTRIDE + kb]);
                a[mi][2] = cvt_tf32(Ab[r * ASTRIDE + kb + 4]);
                a[mi][3] = cvt_tf32(Ab[(r + 8) * ASTRIDE + kb + 4]);
            }
#pragma unroll
            for (int ni = 0; ni < 8; ni++) {
                int n  = warp_n + ni * 8 + (lane >> 2);
                int kb = kk + (lane & 3);
                unsigned b0, b1;
                if (BT) {
                    b0 = cvt_tf32(Bb[n * ASTRIDE + kb]);
                    b1 = cvt_tf32(Bb[n * ASTRIDE + kb + 4]);
                } else {
                    b0 = cvt_tf32(Bb[kb * BSTRIDE_NN + n]);
                    b1 = cvt_tf32(Bb[(kb + 4) * BSTRIDE_NN + n]);
                }
#pragma unroll
                for (int mi = 0; mi < 2; mi++) {
                    asm volatile(
                        "mma.sync.aligned.m16n8k8.row.col.f32.tf32.tf32.f32 "
                        "{%0,%1,%2,%3},{%4,%5,%6,%7},{%8,%9},{%0,%1,%2,%3};"
                        : "+f"(c[mi][ni][0]), "+f"(c[mi][ni][1]),
                          "+f"(c[mi][ni][2]), "+f"(c[mi][ni][3])
                        : "r"(a[mi][0]), "r"(a[mi][1]), "r"(a[mi][2]), "r"(a[mi][3]),
                          "r"(b0), "r"(b1));
                }
            }
        }
        __syncthreads();
    }

    // -------- epilogue --------
#pragma unroll
    for (int mi = 0; mi < 2; mi++) {
        int rbase = m0 + warp_m + mi * 16 + (lane >> 2);
#pragma unroll
        for (int half = 0; half < 2; half++) {
            int row = rbase + half * 8;
            if (row < M) {
                long ro = (long)row * N;
#pragma unroll
                for (int ni = 0; ni < 8; ni++) {
                    int col = n0 + warp_n + ni * 8 + (lane & 3) * 2;
                    float v0 = c[mi][ni][half * 2 + 0];
                    float v1 = c[mi][ni][half * 2 + 1];
                    if (biasp) { v0 += biasp[col]; v1 += biasp[col + 1]; }
                    if (RELU)  { v0 = fmaxf(v0, 0.f); v1 = fmaxf(v1, 0.f); }
                    if (resid) { v0 += resid[ro + col]; v1 += resid[ro + col + 1]; }
                    *(float2*)(Cp + ro + col) = make_float2(v0, v1);
                }
            }
        }
    }
}

// ---------------- layernorm ----------------
__global__ __launch_bounds__(256) void ln_kernel(
    const float* __restrict__ x, const float* __restrict__ w,
    const float* __restrict__ bvec, float* __restrict__ y)
{
    long t = blockIdx.x;
    const float* xr = x + t * DMODEL;
    float* yr = y + t * DMODEL;
    int tid = threadIdx.x;
    float v[4];
    float s = 0.f, s2 = 0.f;
#pragma unroll
    for (int i = 0; i < 4; i++) {
        v[i] = xr[tid + i * 256];
        s += v[i]; s2 += v[i] * v[i];
    }
#pragma unroll
    for (int o = 16; o; o >>= 1) {
        s  += __shfl_xor_sync(0xffffffffu, s, o);
        s2 += __shfl_xor_sync(0xffffffffu, s2, o);
    }
    __shared__ float rs[8], rs2[8];
    if ((tid & 31) == 0) { rs[tid >> 5] = s; rs2[tid >> 5] = s2; }
    __syncthreads();
    float ts = 0.f, ts2 = 0.f;
#pragma unroll
    for (int i = 0; i < 8; i++) { ts += rs[i]; ts2 += rs2[i]; }
    float mean = ts * (1.0f / DMODEL);
    float var  = ts2 * (1.0f / DMODEL) - mean * mean;
    float inv  = rsqrtf(var + 1e-5f);
#pragma unroll
    for (int i = 0; i < 4; i++) {
        int d = tid + i * 256;
        yr[d] = (v[i] - mean) * inv * w[d] + bvec[d];
    }
}

// ---------------- fused attention (one block per (b,h)) ----------------
__global__ __launch_bounds__(256) void attn_kernel(
    const float* __restrict__ qkv, float* __restrict__ ao)
{
    __shared__ float Ks[SEQ * 65];
    __shared__ float Vs[SEQ * 65];
    __shared__ float qb[8][64];
    __shared__ float pb[8][80];

    int bh = blockIdx.x;
    int b = bh >> 4, h = bh & 15;
    int tid = threadIdx.x, lane = tid & 31, wrp = tid >> 5;
    long tok0 = (long)b * SEQ;

    for (int idx = tid; idx < SEQ * 64; idx += 256) {
        int s = idx >> 6, d = idx & 63;
        long off = (tok0 + s) * QKVD + h * 64 + d;
        Ks[s * 65 + d] = qkv[off + DMODEL];
        Vs[s * 65 + d] = qkv[off + 2 * DMODEL];
    }
    __syncthreads();

    for (int s = wrp; s < SEQ; s += 8) {
        long qoff = (tok0 + s) * QKVD + h * 64;
        qb[wrp][lane]      = qkv[qoff + lane];
        qb[wrp][lane + 32] = qkv[qoff + lane + 32];
        __syncwarp();

        float e[3];
        float mx = -1e30f;
#pragma unroll
        for (int jj = 0; jj < 3; jj++) {
            int j = lane + jj * 32;
            float dot = -1e30f;
            if (j < SEQ) {
                const float* kr = Ks + j * 65;
                float a = 0.f;
#pragma unroll
                for (int d = 0; d < 64; d++) a += qb[wrp][d] * kr[d];
                dot = a * 0.125f;
            }
            e[jj] = dot;
            mx = fmaxf(mx, dot);
        }
#pragma unroll
        for (int o = 16; o; o >>= 1) mx = fmaxf(mx, __shfl_xor_sync(0xffffffffu, mx, o));

        float ssum = 0.f;
#pragma unroll
        for (int jj = 0; jj < 3; jj++) {
            int j = lane + jj * 32;
            float p = (j < SEQ) ? __expf(e[jj] - mx) : 0.f;
            e[jj] = p; ssum += p;
        }
#pragma unroll
        for (int o = 16; o; o >>= 1) ssum += __shfl_xor_sync(0xffffffffu, ssum, o);
        float inv = 1.0f / ssum;
#pragma unroll
        for (int jj = 0; jj < 3; jj++) {
            int j = lane + jj * 32;
            if (j < SEQ) pb[wrp][j] = e[jj] * inv;
        }
        __syncwarp();

        float a0 = 0.f, a1 = 0.f;
        for (int j = 0; j < SEQ; j++) {
            float p = pb[wrp][j];
            a0 += p * Vs[j * 65 + lane];
            a1 += p * Vs[j * 65 + lane + 32];
        }
        long orow = (tok0 + s) * DMODEL + h * 64;
        ao[orow + lane]      = a0;
        ao[orow + lane + 32] = a1;
        __syncwarp();
    }
}

// ---------------- router ----------------
__global__ __launch_bounds__(256) void router_kernel(
    const float* __restrict__ ffn, const float* __restrict__ rw,
    int* __restrict__ topi, float* __restrict__ gates)
{
    int b = blockIdx.x;
    const float* xr = ffn + (long)b * SEQ * DMODEL;
    int tid = threadIdx.x;
    int e = tid >> 5, lane = tid & 31;
    const float* wr = rw + e * DMODEL;
    float s = 0.f;
    for (int d = lane; d < DMODEL; d += 32) s += xr[d] * wr[d];
#pragma unroll
    for (int o = 16; o; o >>= 1) s += __shfl_xor_sync(0xffffffffu, s, o);
    __shared__ float lg[NEXP];
    if (lane == 0) lg[e] = s;
    __syncthreads();
    if (tid == 0) {
        int i0 = 0; float v0 = lg[0];
        for (int i = 1; i < NEXP; i++) if (lg[i] > v0) { v0 = lg[i]; i0 = i; }
        int i1 = -1; float v1 = -1e30f;
        for (int i = 0; i < NEXP; i++) if (i != i0 && lg[i] > v1) { v1 = lg[i]; i1 = i; }
        float e1 = __expf(v1 - v0);
        float den = 1.f + e1;
        topi[b * TOPK]     = i0;
        topi[b * TOPK + 1] = i1;
        gates[b * TOPK]     = 1.f / den;
        gates[b * TOPK + 1] = e1 / den;
    }
}

// ---------------- final combine ----------------
__global__ __launch_bounds__(256) void combine_kernel(
    const float* __restrict__ x, const float* __restrict__ sho,
    const float* __restrict__ eo, const float* __restrict__ gates,
    float* __restrict__ out)
{
    long t = blockIdx.x;
    int tid = threadIdx.x;
    int b = (int)(t / SEQ);
    int s = (int)(t - (long)b * SEQ);
    float g0 = gates[b * TOPK], g1 = gates[b * TOPK + 1];
    long base = t * DMODEL;
    long e0 = ((long)(b * TOPK) * SEQ + s) * DMODEL;
    long e1 = e0 + (long)SEQ * DMODEL;
#pragma unroll
    for (int i = 0; i < 4; i++) {
        int d = tid + i * 256;
        out[base + d] = x[base + d] + sho[base + d] + g0 * eo[e0 + d] + g1 * eo[e1 + d];
    }
}

// ---------------- launch ----------------
extern "C" void kernel_launch(void* const* d_in, const int* in_sizes, int n_in,
                              void* d_out, int out_size)
{
    const float* src   = (const float*)d_in[0];
    const float* pw    = (const float*)d_in[1];
    const float* pbias = (const float*)d_in[2];
    const float* ow    = (const float*)d_in[3];
    const float* ob    = (const float*)d_in[4];
    const float* ln1w  = (const float*)d_in[5];
    const float* ln1b  = (const float*)d_in[6];
    const float* ln2w  = (const float*)d_in[7];
    const float* ln2b  = (const float*)d_in[8];
    const float* rw    = (const float*)d_in[9];
    const float* ew1   = (const float*)d_in[10];
    const float* eb1   = (const float*)d_in[11];
    const float* ew2   = (const float*)d_in[12];
    const float* eb2   = (const float*)d_in[13];
    const float* sw1   = (const float*)d_in[14];
    const float* sb1   = (const float*)d_in[15];
    const float* sw2   = (const float*)d_in[16];
    const float* sb2   = (const float*)d_in[17];

    float *xn, *qkv, *ao, *x, *ffn, *hmoe, *eo, *hsh, *sho, *gates;
    int *topi;
    cudaGetSymbolAddress((void**)&xn,   g_xn);
    cudaGetSymbolAddress((void**)&qkv,  g_qkv);
    cudaGetSymbolAddress((void**)&ao,   g_ao);
    cudaGetSymbolAddress((void**)&x,    g_x);
    cudaGetSymbolAddress((void**)&ffn,  g_ffn);
    cudaGetSymbolAddress((void**)&hmoe, g_hmoe);
    cudaGetSymbolAddress((void**)&eo,   g_eo);
    cudaGetSymbolAddress((void**)&hsh,  g_hsh);
    cudaGetSymbolAddress((void**)&sho,  g_sho);
    cudaGetSymbolAddress((void**)&topi, g_topi);
    cudaGetSymbolAddress((void**)&gates,g_gates);

    cudaFuncSetAttribute(tgemm<true,  false>, cudaFuncAttributeMaxDynamicSharedMemorySize, SMEM_BYTES);
    cudaFuncSetAttribute(tgemm<false, true >, cudaFuncAttributeMaxDynamicSharedMemorySize, SMEM_BYTES);
    cudaFuncSetAttribute(tgemm<false, false>, cudaFuncAttributeMaxDynamicSharedMemorySize, SMEM_BYTES);

    const int mt_tok = TOK / 128;   // 77 (exact)

    // 1. LN1
    ln_kernel<<<TOK, 256>>>(src, ln1w, ln1b, xn);
    // 2. QKV = xn @ packed_w^T + packed_b
    tgemm<true, false><<<dim3(QKVD / 128, mt_tok, 1), 256, SMEM_BYTES>>>(
        xn, pw, pbias, nullptr, qkv, TOK, QKVD, DMODEL, 0, 1, 0, 0, 0, nullptr);
    // 3. attention
    attn_kernel<<<NB * NHEAD, 256>>>(qkv, ao);
    // 4. x = src + ao @ out_w^T + out_b
    tgemm<true, false><<<dim3(DMODEL / 128, mt_tok, 1), 256, SMEM_BYTES>>>(
        ao, ow, ob, src, x, TOK, DMODEL, DMODEL, 0, 1, 0, 0, 0, nullptr);
    // 5. LN2
    ln_kernel<<<TOK, 256>>>(x, ln2w, ln2b, ffn);
    // 6. router top-2
    router_kernel<<<NB, 256>>>(ffn, rw, topi, gates);
    // 7. MoE layer 1: h = relu(ffn[b] @ ew1[e] + eb1[e])
    tgemm<false, true><<<dim3(FF / 128, 1, NB * TOPK), 256, SMEM_BYTES>>>(
        ffn, ew1, eb1, nullptr, hmoe, SEQ, FF, DMODEL,
        (long)SEQ * DMODEL, TOPK, (long)DMODEL * FF, FF, (long)SEQ * FF, topi);
    // 8. MoE layer 2: eo = h @ ew2[e] + eb2[e]
    tgemm<false, false><<<dim3(DMODEL / 128, 1, NB * TOPK), 256, SMEM_BYTES>>>(
        hmoe, ew2, eb2, nullptr, eo, SEQ, DMODEL, FF,
        (long)SEQ * FF, 1, (long)FF * DMODEL, DMODEL, (long)SEQ * DMODEL, topi);
    // 9. shared expert layer 1: hsh = relu(ffn @ sw1 + sb1)
    tgemm<false, true><<<dim3(FF / 128, mt_tok, 1), 256, SMEM_BYTES>>>(
        ffn, sw1, sb1, nullptr, hsh, TOK, FF, DMODEL, 0, 1, 0, 0, 0, nullptr);
    // 10. shared expert layer 2: sho = hsh @ sw2 + sb2
    tgemm<false, false><<<dim3(DMODEL / 128, mt_tok, 1), 256, SMEM_BYTES>>>(
        hsh, sw2, sb2, nullptr, sho, TOK, DMODEL, FF, 0, 1, 0, 0, 0, nullptr);
    // 11. out = x + moe + shared
    combine_kernel<<<TOK, 256>>>(x, sho, eo, gates, (float*)d_out);
}

// round 4
// speedup vs baseline: 6.0049x; 1.5623x over previous
#include <cuda_runtime.h>
#include <cuda_bf16.h>

// ---------------- problem constants ----------------
#define NB      128
#define SEQ     77
#define DMODEL  1024
#define NHEAD   16
#define FF      4096
#define NEXP    8
#define TOPK    2
#define TOK     (NB * SEQ)          // 9856
#define QKVD    (3 * DMODEL)        // 3072

typedef __nv_bfloat16 bf16;

// ---------------- scratch (device globals; no allocation) ----------------
__device__ float g_xn  [(size_t)TOK * DMODEL];
__device__ float g_qkv [(size_t)TOK * QKVD];
__device__ float g_ao  [(size_t)TOK * DMODEL];
__device__ float g_x   [(size_t)TOK * DMODEL];
__device__ float g_ffn [(size_t)TOK * DMODEL];
__device__ bf16  g_ffnb[(size_t)TOK * DMODEL];
__device__ bf16  g_hmoe[(size_t)NB * TOPK * SEQ * FF];
__device__ float g_eo  [(size_t)NB * TOPK * SEQ * DMODEL];
__device__ bf16  g_hsh [(size_t)TOK * FF];
__device__ float g_sho [(size_t)TOK * DMODEL];
__device__ int   g_topi [NB * TOPK];
__device__ float g_gates[NB * TOPK];
// transposed bf16 weights
__device__ bf16 g_ew1t[(size_t)NEXP * FF * DMODEL];
__device__ bf16 g_ew2t[(size_t)NEXP * DMODEL * FF];
__device__ bf16 g_sw1t[(size_t)FF * DMODEL];
__device__ bf16 g_sw2t[(size_t)DMODEL * FF];

// ---------------- helpers ----------------
__device__ __forceinline__ unsigned cvt_tf32(float x) {
    unsigned r;
    asm("cvt.rna.tf32.f32 %0, %1;" : "=r"(r) : "f"(x));
    return r;
}
__device__ __forceinline__ void cp_async16(void* dst, const void* src, int sz) {
    unsigned saddr = (unsigned)__cvta_generic_to_shared(dst);
    asm volatile("cp.async.cg.shared.global [%0], [%1], 16, %2;\n"
                 :: "r"(saddr), "l"(src), "r"(sz));
}
__device__ __forceinline__ void cp_commit() {
    asm volatile("cp.async.commit_group;\n");
}
__device__ __forceinline__ void cp_wait1() {
    asm volatile("cp.async.wait_group 1;\n");
}

// ================= bf16 tensor-core GEMM (all B pre-transposed [N][K]) =====
// C[z] = epi( A[z/aDiv] @ B[widx]^T + bias[widx] )
#define AS 40                     // smem k-pitch in bf16 (80B): conflict-free
#define TBUF (128 * AS)           // 5120 bf16 per tile buffer

template<bool RELU, bool OUTBF>
__global__ void __launch_bounds__(256, 2) bgemm(
    const bf16* __restrict__ A, const bf16* __restrict__ Bm,
    const float* __restrict__ bias, void* __restrict__ C,
    int M, int N, int K,
    long sA, int aDiv, long sB, long sBias, long sC,
    const int* __restrict__ eIdx)
{
    __shared__ bf16 sh[4 * TBUF];          // 40 KB
    bf16* As0 = sh;            bf16* As1 = sh + TBUF;
    bf16* Bs0 = sh + 2 * TBUF; bf16* Bs1 = sh + 3 * TBUF;

    int z = blockIdx.z;
    int widx = eIdx ? eIdx[z] : z;
    const bf16* Ap = A + (long)(z / aDiv) * sA;
    const bf16* Bp = Bm + (long)widx * sB;
    const float* biasp = bias ? (bias + (long)widx * sBias) : nullptr;

    int m0 = blockIdx.y * 128;
    int n0 = blockIdx.x * 128;
    int tid = threadIdx.x, lane = tid & 31, w = tid >> 5;
    int warp_m = (w & 3) * 32;
    int warp_n = (w >> 2) * 64;

    float c[2][8][4];
#pragma unroll
    for (int i = 0; i < 2; i++)
#pragma unroll
        for (int j = 0; j < 8; j++)
#pragma unroll
            for (int q = 0; q < 4; q++) c[i][j][q] = 0.f;

    const int nChunks = K >> 5;

    auto copyA = [&](int k0, bf16* dst) {
#pragma unroll
        for (int i = 0; i < 2; i++) {
            int f = tid + i * 256;
            int row = f >> 2;            // 0..127
            int kq  = (f & 3) * 8;       // bf16 offset 0,8,16,24
            int gr = m0 + row;
            int sz = (gr < M) ? 16 : 0;
            const bf16* src = Ap + (long)(gr < M ? gr : 0) * K + k0 + kq;
            cp_async16(dst + row * AS + kq, src, sz);
        }
    };
    auto copyB = [&](int k0, bf16* dst) {
#pragma unroll
        for (int i = 0; i < 2; i++) {
            int f = tid + i * 256;
            int row = f >> 2;
            int kq  = (f & 3) * 8;
            const bf16* src = Bp + (long)(n0 + row) * K + k0 + kq;
            cp_async16(dst + row * AS + kq, src, 16);
        }
    };

    copyA(0, As0); copyB(0, Bs0);
    cp_commit();

    for (int ch = 0; ch < nChunks; ch++) {
        if (ch + 1 < nChunks) {
            copyA((ch + 1) << 5, (ch & 1) ? As0 : As1);
            copyB((ch + 1) << 5, (ch & 1) ? Bs0 : Bs1);
        }
        cp_commit();
        cp_wait1();
        __syncthreads();

        const bf16* Ab = (ch & 1) ? As1 : As0;
        const bf16* Bb = (ch & 1) ? Bs1 : Bs0;

#pragma unroll
        for (int kk = 0; kk < 32; kk += 16) {
            int kb = kk + (lane & 3) * 2;
            unsigned a[2][4];
#pragma unroll
            for (int mi = 0; mi < 2; mi++) {
                int r = warp_m + mi * 16 + (lane >> 2);
                a[mi][0] = *(const unsigned*)(Ab + r * AS + kb);
                a[mi][1] = *(const unsigned*)(Ab + (r + 8) * AS + kb);
                a[mi][2] = *(const unsigned*)(Ab + r * AS + kb + 8);
                a[mi][3] = *(const unsigned*)(Ab + (r + 8) * AS + kb + 8);
            }
#pragma unroll
            for (int ni = 0; ni < 8; ni++) {
                int n = warp_n + ni * 8 + (lane >> 2);
                unsigned b0 = *(const unsigned*)(Bb + n * AS + kb);
                unsigned b1 = *(const unsigned*)(Bb + n * AS + kb + 8);
#pragma unroll
                for (int mi = 0; mi < 2; mi++) {
                    asm volatile(
                        "mma.sync.aligned.m16n8k16.row.col.f32.bf16.bf16.f32 "
                        "{%0,%1,%2,%3},{%4,%5,%6,%7},{%8,%9},{%0,%1,%2,%3};"
                        : "+f"(c[mi][ni][0]), "+f"(c[mi][ni][1]),
                          "+f"(c[mi][ni][2]), "+f"(c[mi][ni][3])
                        : "r"(a[mi][0]), "r"(a[mi][1]), "r"(a[mi][2]), "r"(a[mi][3]),
                          "r"(b0), "r"(b1));
                }
            }
        }
        __syncthreads();
    }

    // -------- epilogue --------
    long cbase = (long)z * sC;
#pragma unroll
    for (int mi = 0; mi < 2; mi++) {
#pragma unroll
        for (int half = 0; half < 2; half++) {
            int row = m0 + warp_m + mi * 16 + (lane >> 2) + half * 8;
            if (row < M) {
                long ro = cbase + (long)row * N;
#pragma unroll
                for (int ni = 0; ni < 8; ni++) {
                    int col = n0 + warp_n + ni * 8 + (lane & 3) * 2;
                    float v0 = c[mi][ni][half * 2 + 0];
                    float v1 = c[mi][ni][half * 2 + 1];
                    if (biasp) { v0 += biasp[col]; v1 += biasp[col + 1]; }
                    if (RELU)  { v0 = fmaxf(v0, 0.f); v1 = fmaxf(v1, 0.f); }
                    if (OUTBF) {
                        __nv_bfloat162 p = __float22bfloat162_rn(make_float2(v0, v1));
                        *(__nv_bfloat162*)((bf16*)C + ro + col) = p;
                    } else {
                        *(float2*)((float*)C + ro + col) = make_float2(v0, v1);
                    }
                }
            }
        }
    }
}

// ================= TF32 GEMM (QKV + out-proj; B row-major [N,K]) ==========
#define ASTRIDE   36
#define ABUF (128 * ASTRIDE)
#define SMEM_BYTES  (4 * ABUF * 4)    // 73728

template<bool RELU>
__global__ void __launch_bounds__(256, 2) tgemm(
    const float* __restrict__ A, const float* __restrict__ Bm,
    const float* __restrict__ bias, const float* __restrict__ resid,
    float* __restrict__ C, int M, int N, int K)
{
    extern __shared__ float sm[];
    float* As = sm;
    float* Bs = sm + 2 * ABUF;

    int m0 = blockIdx.y * 128;
    int n0 = blockIdx.x * 128;
    int tid = threadIdx.x, lane = tid & 31, w = tid >> 5;
    int warp_m = (w & 3) * 32;
    int warp_n = (w >> 2) * 64;

    float c[2][8][4];
#pragma unroll
    for (int i = 0; i < 2; i++)
#pragma unroll
        for (int j = 0; j < 8; j++)
#pragma unroll
            for (int q = 0; q < 4; q++) c[i][j][q] = 0.f;

    const int nChunks = K >> 5;

    auto copyA = [&](int k0, int buf) {
        float* dst = As + buf * ABUF;
#pragma unroll
        for (int i = 0; i < 4; i++) {
            int f = tid + i * 256;
            int row = f >> 3;
            int kq  = (f & 7) * 4;
            int gr = m0 + row;
            int sz = (gr < M) ? 16 : 0;
            const float* src = A + (long)(gr < M ? gr : 0) * K + k0 + kq;
            cp_async16(dst + row * ASTRIDE + kq, src, sz);
        }
    };
    auto copyB = [&](int k0, int buf) {
        float* dst = Bs + buf * ABUF;
#pragma unroll
        for (int i = 0; i < 4; i++) {
            int f = tid + i * 256;
            int row = f >> 3;
            int kq  = (f & 7) * 4;
            const float* src = Bm + (long)(n0 + row) * K + k0 + kq;
            cp_async16(dst + row * ASTRIDE + kq, src, 16);
        }
    };

    copyA(0, 0); copyB(0, 0);
    cp_commit();

    for (int ch = 0; ch < nChunks; ch++) {
        if (ch + 1 < nChunks) {
            copyA((ch + 1) << 5, (ch + 1) & 1);
            copyB((ch + 1) << 5, (ch + 1) & 1);
        }
        cp_commit();
        cp_wait1();
        __syncthreads();

        const float* Ab = As + (ch & 1) * ABUF;
        const float* Bb = Bs + (ch & 1) * ABUF;

#pragma unroll
        for (int kk = 0; kk < 32; kk += 8) {
            int kb = kk + (lane & 3);
            unsigned a[2][4];
#pragma unroll
            for (int mi = 0; mi < 2; mi++) {
                int r = warp_m + mi * 16 + (lane >> 2);
                a[mi][0] = cvt_tf32(Ab[r * ASTRIDE + kb]);
                a[mi][1] = cvt_tf32(Ab[(r + 8) * ASTRIDE + kb]);
                a[mi][2] = cvt_tf32(Ab[r * ASTRIDE + kb + 4]);
                a[mi][3] = cvt_tf32(Ab[(r + 8) * ASTRIDE + kb + 4]);
            }
#pragma unroll
            for (int ni = 0; ni < 8; ni++) {
                int n = warp_n + ni * 8 + (lane >> 2);
                unsigned b0 = cvt_tf32(Bb[n * ASTRIDE + kb]);
                unsigned b1 = cvt_tf32(Bb[n * ASTRIDE + kb + 4]);
#pragma unroll
                for (int mi = 0; mi < 2; mi++) {
                    asm volatile(
                        "mma.sync.aligned.m16n8k8.row.col.f32.tf32.tf32.f32 "
                        "{%0,%1,%2,%3},{%4,%5,%6,%7},{%8,%9},{%0,%1,%2,%3};"
                        : "+f"(c[mi][ni][0]), "+f"(c[mi][ni][1]),
                          "+f"(c[mi][ni][2]), "+f"(c[mi][ni][3])
                        : "r"(a[mi][0]), "r"(a[mi][1]), "r"(a[mi][2]), "r"(a[mi][3]),
                          "r"(b0), "r"(b1));
                }
            }
        }
        __syncthreads();
    }

#pragma unroll
    for (int mi = 0; mi < 2; mi++) {
#pragma unroll
        for (int half = 0; half < 2; half++) {
            int row = m0 + warp_m + mi * 16 + (lane >> 2) + half * 8;
            if (row < M) {
                long ro = (long)row * N;
#pragma unroll
                for (int ni = 0; ni < 8; ni++) {
                    int col = n0 + warp_n + ni * 8 + (lane & 3) * 2;
                    float v0 = c[mi][ni][half * 2 + 0];
                    float v1 = c[mi][ni][half * 2 + 1];
                    if (bias)  { v0 += bias[col]; v1 += bias[col + 1]; }
                    if (RELU)  { v0 = fmaxf(v0, 0.f); v1 = fmaxf(v1, 0.f); }
                    if (resid) { v0 += resid[ro + col]; v1 += resid[ro + col + 1]; }
                    *(float2*)(C + ro + col) = make_float2(v0, v1);
                }
            }
        }
    }
}

// ---------------- transpose + convert fp32 [R,C] -> bf16 [C,R] -------------
__global__ __launch_bounds__(256) void tconv_kernel(
    const float* __restrict__ in, bf16* __restrict__ out, int R, int C)
{
    __shared__ float tile[32][33];
    long zoff = (long)blockIdx.z * R * C;
    in += zoff; out += zoff;
    int tx = threadIdx.x & 31, ty = threadIdx.x >> 5;   // 32 x 8
    int c0 = blockIdx.x * 32, r0 = blockIdx.y * 32;
#pragma unroll
    for (int j = 0; j < 4; j++)
        tile[ty + j * 8][tx] = in[(long)(r0 + ty + j * 8) * C + c0 + tx];
    __syncthreads();
#pragma unroll
    for (int j = 0; j < 4; j++)
        out[(long)(c0 + ty + j * 8) * R + r0 + tx] =
            __float2bfloat16_rn(tile[tx][ty + j * 8]);
}

// ---------------- layernorm (optional dual fp32+bf16 output) --------------
__global__ __launch_bounds__(256) void ln_kernel(
    const float* __restrict__ x, const float* __restrict__ w,
    const float* __restrict__ bvec, float* __restrict__ y,
    bf16* __restrict__ yb)
{
    long t = blockIdx.x;
    const float* xr = x + t * DMODEL;
    float* yr = y + t * DMODEL;
    int tid = threadIdx.x;
    float v[4];
    float s = 0.f, s2 = 0.f;
#pragma unroll
    for (int i = 0; i < 4; i++) {
        v[i] = xr[tid + i * 256];
        s += v[i]; s2 += v[i] * v[i];
    }
#pragma unroll
    for (int o = 16; o; o >>= 1) {
        s  += __shfl_xor_sync(0xffffffffu, s, o);
        s2 += __shfl_xor_sync(0xffffffffu, s2, o);
    }
    __shared__ float rs[8], rs2[8];
    if ((tid & 31) == 0) { rs[tid >> 5] = s; rs2[tid >> 5] = s2; }
    __syncthreads();
    float ts = 0.f, ts2 = 0.f;
#pragma unroll
    for (int i = 0; i < 8; i++) { ts += rs[i]; ts2 += rs2[i]; }
    float mean = ts * (1.0f / DMODEL);
    float var  = ts2 * (1.0f / DMODEL) - mean * mean;
    float inv  = rsqrtf(var + 1e-5f);
#pragma unroll
    for (int i = 0; i < 4; i++) {
        int d = tid + i * 256;
        float o = (v[i] - mean) * inv * w[d] + bvec[d];
        yr[d] = o;
        if (yb) yb[t * DMODEL + d] = __float2bfloat16_rn(o);
    }
}

// ---------------- fused attention (one block per (b,h)) -------------------
__global__ __launch_bounds__(256) void attn_kernel(
    const float* __restrict__ qkv, float* __restrict__ ao)
{
    __shared__ float Ks[SEQ * 65];
    __shared__ float Vs[SEQ * 65];
    __shared__ float qb[8][64];
    __shared__ float pb[8][80];

    int bh = blockIdx.x;
    int b = bh >> 4, h = bh & 15;
    int tid = threadIdx.x, lane = tid & 31, wrp = tid >> 5;
    long tok0 = (long)b * SEQ;

    for (int idx = tid; idx < SEQ * 64; idx += 256) {
        int s = idx >> 6, d = idx & 63;
        long off = (tok0 + s) * QKVD + h * 64 + d;
        Ks[s * 65 + d] = qkv[off + DMODEL];
        Vs[s * 65 + d] = qkv[off + 2 * DMODEL];
    }
    __syncthreads();

    for (int s = wrp; s < SEQ; s += 8) {
        long qoff = (tok0 + s) * QKVD + h * 64;
        qb[wrp][lane]      = qkv[qoff + lane];
        qb[wrp][lane + 32] = qkv[qoff + lane + 32];
        __syncwarp();

        float e[3];
        float mx = -1e30f;
#pragma unroll
        for (int jj = 0; jj < 3; jj++) {
            int j = lane + jj * 32;
            float dot = -1e30f;
            if (j < SEQ) {
                const float* kr = Ks + j * 65;
                float a = 0.f;
#pragma unroll
                for (int d = 0; d < 64; d++) a += qb[wrp][d] * kr[d];
                dot = a * 0.125f;
            }
            e[jj] = dot;
            mx = fmaxf(mx, dot);
        }
#pragma unroll
        for (int o = 16; o; o >>= 1) mx = fmaxf(mx, __shfl_xor_sync(0xffffffffu, mx, o));

        float ssum = 0.f;
#pragma unroll
        for (int jj = 0; jj < 3; jj++) {
            int j = lane + jj * 32;
            float p = (j < SEQ) ? __expf(e[jj] - mx) : 0.f;
            e[jj] = p; ssum += p;
        }
#pragma unroll
        for (int o = 16; o; o >>= 1) ssum += __shfl_xor_sync(0xffffffffu, ssum, o);
        float inv = 1.0f / ssum;
#pragma unroll
        for (int jj = 0; jj < 3; jj++) {
            int j = lane + jj * 32;
            if (j < SEQ) pb[wrp][j] = e[jj] * inv;
        }
        __syncwarp();

        float a0 = 0.f, a1 = 0.f;
        for (int j = 0; j < SEQ; j++) {
            float p = pb[wrp][j];
            a0 += p * Vs[j * 65 + lane];
            a1 += p * Vs[j * 65 + lane + 32];
        }
        long orow = (tok0 + s) * DMODEL + h * 64;
        ao[orow + lane]      = a0;
        ao[orow + lane + 32] = a1;
        __syncwarp();
    }
}

// ---------------- router ----------------
__global__ __launch_bounds__(256) void router_kernel(
    const float* __restrict__ ffn, const float* __restrict__ rw,
    int* __restrict__ topi, float* __restrict__ gates)
{
    int b = blockIdx.x;
    const float* xr = ffn + (long)b * SEQ * DMODEL;
    int tid = threadIdx.x;
    int e = tid >> 5, lane = tid & 31;
    const float* wr = rw + e * DMODEL;
    float s = 0.f;
    for (int d = lane; d < DMODEL; d += 32) s += xr[d] * wr[d];
#pragma unroll
    for (int o = 16; o; o >>= 1) s += __shfl_xor_sync(0xffffffffu, s, o);
    __shared__ float lg[NEXP];
    if (lane == 0) lg[e] = s;
    __syncthreads();
    if (tid == 0) {
        int i0 = 0; float v0 = lg[0];
        for (int i = 1; i < NEXP; i++) if (lg[i] > v0) { v0 = lg[i]; i0 = i; }
        int i1 = -1; float v1 = -1e30f;
        for (int i = 0; i < NEXP; i++) if (i != i0 && lg[i] > v1) { v1 = lg[i]; i1 = i; }
        float e1 = __expf(v1 - v0);
        float den = 1.f + e1;
        topi[b * TOPK]     = i0;
        topi[b * TOPK + 1] = i1;
        gates[b * TOPK]     = 1.f / den;
        gates[b * TOPK + 1] = e1 / den;
    }
}

// ---------------- final combine ----------------
__global__ __launch_bounds__(256) void combine_kernel(
    const float* __restrict__ x, const float* __restrict__ sho,
    const float* __restrict__ eo, const float* __restrict__ gates,
    float* __restrict__ out)
{
    long t = blockIdx.x;
    int tid = threadIdx.x;
    int b = (int)(t / SEQ);
    int s = (int)(t - (long)b * SEQ);
    float g0 = gates[b * TOPK], g1 = gates[b * TOPK + 1];
    long base = t * DMODEL;
    long e0 = ((long)(b * TOPK) * SEQ + s) * DMODEL;
    long e1 = e0 + (long)SEQ * DMODEL;
#pragma unroll
    for (int i = 0; i < 4; i++) {
        int d = tid + i * 256;
        out[base + d] = x[base + d] + sho[base + d] + g0 * eo[e0 + d] + g1 * eo[e1 + d];
    }
}

// ---------------- launch ----------------
extern "C" void kernel_launch(void* const* d_in, const int* in_sizes, int n_in,
                              void* d_out, int out_size)
{
    const float* src   = (const float*)d_in[0];
    const float* pw    = (const float*)d_in[1];
    const float* pbias = (const float*)d_in[2];
    const float* ow    = (const float*)d_in[3];
    const float* ob    = (const float*)d_in[4];
    const float* ln1w  = (const float*)d_in[5];
    const float* ln1b  = (const float*)d_in[6];
    const float* ln2w  = (const float*)d_in[7];
    const float* ln2b  = (const float*)d_in[8];
    const float* rw    = (const float*)d_in[9];
    const float* ew1   = (const float*)d_in[10];
    const float* eb1   = (const float*)d_in[11];
    const float* ew2   = (const float*)d_in[12];
    const float* eb2   = (const float*)d_in[13];
    const float* sw1   = (const float*)d_in[14];
    const float* sb1   = (const float*)d_in[15];
    const float* sw2   = (const float*)d_in[16];
    const float* sb2   = (const float*)d_in[17];

    float *xn, *qkv, *ao, *x, *ffn, *eo, *sho, *gates;
    bf16 *ffnb, *hmoe, *hsh, *ew1t, *ew2t, *sw1t, *sw2t;
    int *topi;
    cudaGetSymbolAddress((void**)&xn,   g_xn);
    cudaGetSymbolAddress((void**)&qkv,  g_qkv);
    cudaGetSymbolAddress((void**)&ao,   g_ao);
    cudaGetSymbolAddress((void**)&x,    g_x);
    cudaGetSymbolAddress((void**)&ffn,  g_ffn);
    cudaGetSymbolAddress((void**)&ffnb, g_ffnb);
    cudaGetSymbolAddress((void**)&hmoe, g_hmoe);
    cudaGetSymbolAddress((void**)&eo,   g_eo);
    cudaGetSymbolAddress((void**)&hsh,  g_hsh);
    cudaGetSymbolAddress((void**)&sho,  g_sho);
    cudaGetSymbolAddress((void**)&topi, g_topi);
    cudaGetSymbolAddress((void**)&gates,g_gates);
    cudaGetSymbolAddress((void**)&ew1t, g_ew1t);
    cudaGetSymbolAddress((void**)&ew2t, g_ew2t);
    cudaGetSymbolAddress((void**)&sw1t, g_sw1t);
    cudaGetSymbolAddress((void**)&sw2t, g_sw2t);

    cudaFuncSetAttribute(tgemm<false>, cudaFuncAttributeMaxDynamicSharedMemorySize, SMEM_BYTES);

    const int mt_tok = TOK / 128;   // 77 (exact)

    // 0. weight convert+transpose (independent of activations)
    tconv_kernel<<<dim3(FF / 32, DMODEL / 32, NEXP), 256>>>(ew1, ew1t, DMODEL, FF);
    tconv_kernel<<<dim3(DMODEL / 32, FF / 32, NEXP), 256>>>(ew2, ew2t, FF, DMODEL);
    tconv_kernel<<<dim3(FF / 32, DMODEL / 32, 1),    256>>>(sw1, sw1t, DMODEL, FF);
    tconv_kernel<<<dim3(DMODEL / 32, FF / 32, 1),    256>>>(sw2, sw2t, FF, DMODEL);

    // 1. LN1 (fp32 only)
    ln_kernel<<<TOK, 256>>>(src, ln1w, ln1b, xn, nullptr);
    // 2. QKV = xn @ packed_w^T + packed_b   (TF32)
    tgemm<false><<<dim3(QKVD / 128, mt_tok, 1), 256, SMEM_BYTES>>>(
        xn, pw, pbias, nullptr, qkv, TOK, QKVD, DMODEL);
    // 3. attention
    attn_kernel<<<NB * NHEAD, 256>>>(qkv, ao);
    // 4. x = src + ao @ out_w^T + out_b     (TF32)
    tgemm<false><<<dim3(DMODEL / 128, mt_tok, 1), 256, SMEM_BYTES>>>(
        ao, ow, ob, src, x, TOK, DMODEL, DMODEL);
    // 5. LN2 -> fp32 (router) + bf16 (GEMM A)
    ln_kernel<<<TOK, 256>>>(x, ln2w, ln2b, ffn, ffnb);
    // 6. router top-2
    router_kernel<<<NB, 256>>>(ffn, rw, topi, gates);
    // 7. MoE layer 1: hmoe = relu(ffnb[b] @ ew1t[e]^T + eb1[e])  -> bf16
    bgemm<true, true><<<dim3(FF / 128, 1, NB * TOPK), 256>>>(
        ffnb, ew1t, eb1, hmoe, SEQ, FF, DMODEL,
        (long)SEQ * DMODEL, TOPK, (long)FF * DMODEL, FF, (long)SEQ * FF, topi);
    // 8. MoE layer 2: eo = hmoe @ ew2t[e]^T + eb2[e]  -> fp32
    bgemm<false, false><<<dim3(DMODEL / 128, 1, NB * TOPK), 256>>>(
        hmoe, ew2t, eb2, eo, SEQ, DMODEL, FF,
        (long)SEQ * FF, 1, (long)DMODEL * FF, DMODEL, (long)SEQ * DMODEL, topi);
    // 9. shared layer 1: hsh = relu(ffnb @ sw1t^T + sb1)  -> bf16
    bgemm<true, true><<<dim3(FF / 128, mt_tok, 1), 256>>>(
        ffnb, sw1t, sb1, hsh, TOK, FF, DMODEL, 0, 1, 0, 0, 0, nullptr);
    // 10. shared layer 2: sho = hsh @ sw2t^T + sb2  -> fp32
    bgemm<false, false><<<dim3(DMODEL / 128, mt_tok, 1), 256>>>(
        hsh, sw2t, sb2, sho, TOK, DMODEL, FF, 0, 1, 0, 0, 0, nullptr);
    // 11. out = x + moe + shared
    combine_kernel<<<TOK, 256>>>(x, sho, eo, gates, (float*)d_out);
}

// round 5
// speedup vs baseline: 6.9515x; 1.1576x over previous
#include <cuda_runtime.h>
#include <cuda_bf16.h>

// ---------------- problem constants ----------------
#define NB      128
#define SEQ     77
#define DMODEL  1024
#define NHEAD   16
#define FF      4096
#define NEXP    8
#define TOPK    2
#define TOK     (NB * SEQ)          // 9856
#define QKVD    (3 * DMODEL)        // 3072
#define NPAIR   (NB * TOPK)         // 256
#define TOTROWS (NPAIR * SEQ)       // 19712
#define MAXT    162                 // max single-expert M-tiles

typedef __nv_bfloat16 bf16;

// ---------------- scratch (device globals; no allocation) ----------------
__device__ float g_xn  [(size_t)TOK * DMODEL];
__device__ float g_qkv [(size_t)TOK * QKVD];
__device__ float g_ao  [(size_t)TOK * DMODEL];
__device__ float g_x   [(size_t)TOK * DMODEL];
__device__ float g_ffn [(size_t)TOK * DMODEL];
__device__ bf16  g_ffnb[(size_t)TOK * DMODEL];
__device__ bf16  g_hmoe[(size_t)TOTROWS * FF];      // expert-sorted rows
__device__ float g_eo  [(size_t)TOTROWS * DMODEL];  // pair-indexed
__device__ bf16  g_hsh [(size_t)TOK * FF];
__device__ float g_sho [(size_t)TOK * DMODEL];
__device__ int   g_topi [NPAIR];
__device__ float g_gates[NPAIR];
// routing/tiling tables
__device__ int g_order[NPAIR];
__device__ int g_tileE[MAXT];
__device__ int g_tileR[MAXT];
__device__ int g_tileM[MAXT];
__device__ int g_ntiles;
// transposed bf16 weights
__device__ bf16 g_ew1t[(size_t)NEXP * FF * DMODEL];
__device__ bf16 g_ew2t[(size_t)NEXP * DMODEL * FF];
__device__ bf16 g_sw1t[(size_t)FF * DMODEL];
__device__ bf16 g_sw2t[(size_t)DMODEL * FF];

// ---------------- helpers ----------------
__device__ __forceinline__ unsigned cvt_tf32(float x) {
    unsigned r;
    asm("cvt.rna.tf32.f32 %0, %1;" : "=r"(r) : "f"(x));
    return r;
}
__device__ __forceinline__ void cp_async16(void* dst, const void* src, int sz) {
    unsigned saddr = (unsigned)__cvta_generic_to_shared(dst);
    asm volatile("cp.async.cg.shared.global [%0], [%1], 16, %2;\n"
                 :: "r"(saddr), "l"(src), "r"(sz));
}
__device__ __forceinline__ void cp_commit() {
    asm volatile("cp.async.commit_group;\n");
}
__device__ __forceinline__ void cp_wait1() {
    asm volatile("cp.async.wait_group 1;\n");
}
__device__ __forceinline__ void cp_wait2() {
    asm volatile("cp.async.wait_group 2;\n");
}

// ================= bf16 tensor-core GEMM =================
// MODE 0: plain          A rows m0+i,                 C rows m0+i
// MODE 1: MoE layer 1    A rows gathered via order[], C rows sorted (rowbase+i)
// MODE 2: MoE layer 2    A rows sorted (contiguous),  C rows scattered via order[]
// B always pre-transposed bf16 [N][K]; expert weights selected by tile table.
#define AS 40                     // smem k-pitch in bf16 (80B): conflict-free
#define TBUF (128 * AS)           // 5120 bf16 per tile buffer
#define BGSMEM (6 * TBUF * (int)sizeof(bf16))   // 61440 B (3-stage A+B)

template<int MODE, bool RELU, bool OUTBF>
__global__ void __launch_bounds__(256, 2) bgemm(
    const bf16* __restrict__ A, const bf16* __restrict__ Bm,
    const float* __restrict__ bias, void* __restrict__ C,
    int M, int N, int K,
    const int* __restrict__ order, const int* __restrict__ tileE,
    const int* __restrict__ tileR, const int* __restrict__ tileM,
    const int* __restrict__ ntiles)
{
    extern __shared__ bf16 sh[];

    int ty = blockIdx.y;
    int expert = 0, rowbase = 0, Mloc = 128, m0 = 0;
    if (MODE == 0) {
        m0 = ty * 128;
        Mloc = M - m0; if (Mloc > 128) Mloc = 128;
    } else {
        if (ty >= *ntiles) return;
        expert  = tileE[ty];
        rowbase = tileR[ty];
        Mloc    = tileM[ty];
    }
    const bf16* Bp = Bm + (long)expert * N * K;
    const float* biasp = bias ? (bias + (long)expert * N) : nullptr;

    int n0 = blockIdx.x * 128;
    int tid = threadIdx.x, lane = tid & 31, w = tid >> 5;
    int warp_m = (w & 3) * 32;
    int warp_n = (w >> 2) * 64;

    // ---- precompute per-thread load row pointers ----
    int i0 = tid >> 2;              // 0..63
    int kq = (tid & 3) * 8;         // bf16 offset 0,8,16,24
    const bf16* arow[2]; int asz[2];
    const bf16* brow[2];
#pragma unroll
    for (int j = 0; j < 2; j++) {
        int i = i0 + j * 64;
        bool valid = i < Mloc;
        asz[j] = valid ? 16 : 0;
        if (MODE == 0) {
            int gr = m0 + i;
            arow[j] = A + (long)(valid ? gr : 0) * K;
        } else if (MODE == 1) {
            int r = rowbase + i;
            int rc = r < TOTROWS ? r : TOTROWS - 1;
            int p = order[rc / SEQ];
            int s = rc % SEQ;
            int b = p / TOPK;
            arow[j] = A + ((long)b * SEQ + s) * K;
        } else {
            int r = rowbase + i;
            arow[j] = A + (long)(valid ? r : 0) * K;
        }
        brow[j] = Bp + (long)(n0 + i) * K;
    }

    float c[2][8][4];
#pragma unroll
    for (int i = 0; i < 2; i++)
#pragma unroll
        for (int j = 0; j < 8; j++)
#pragma unroll
            for (int q = 0; q < 4; q++) c[i][j][q] = 0.f;

    const int nChunks = K >> 5;

    auto loadChunk = [&](int k0, int buf) {
        bf16* Ad = sh + buf * TBUF;
        bf16* Bd = sh + (3 + buf) * TBUF;
#pragma unroll
        for (int j = 0; j < 2; j++) {
            int i = i0 + j * 64;
            cp_async16(Ad + i * AS + kq, arow[j] + k0 + kq, asz[j]);
            cp_async16(Bd + i * AS + kq, brow[j] + k0 + kq, 16);
        }
    };

    loadChunk(0, 0); cp_commit();
    if (nChunks > 1) loadChunk(32, 1);
    cp_commit();

    for (int ch = 0; ch < nChunks; ch++) {
        if (ch + 2 < nChunks) loadChunk((ch + 2) << 5, (ch + 2) % 3);
        cp_commit();
        cp_wait2();
        __syncthreads();

        const bf16* Ab = sh + (ch % 3) * TBUF;
        const bf16* Bb = sh + (3 + ch % 3) * TBUF;

#pragma unroll
        for (int kk = 0; kk < 32; kk += 16) {
            int kb = kk + (lane & 3) * 2;
            unsigned a[2][4];
#pragma unroll
            for (int mi = 0; mi < 2; mi++) {
                int r = warp_m + mi * 16 + (lane >> 2);
                a[mi][0] = *(const unsigned*)(Ab + r * AS + kb);
                a[mi][1] = *(const unsigned*)(Ab + (r + 8) * AS + kb);
                a[mi][2] = *(const unsigned*)(Ab + r * AS + kb + 8);
                a[mi][3] = *(const unsigned*)(Ab + (r + 8) * AS + kb + 8);
            }
#pragma unroll
            for (int ni = 0; ni < 8; ni++) {
                int n = warp_n + ni * 8 + (lane >> 2);
                unsigned b0 = *(const unsigned*)(Bb + n * AS + kb);
                unsigned b1 = *(const unsigned*)(Bb + n * AS + kb + 8);
#pragma unroll
                for (int mi = 0; mi < 2; mi++) {
                    asm volatile(
                        "mma.sync.aligned.m16n8k16.row.col.f32.bf16.bf16.f32 "
                        "{%0,%1,%2,%3},{%4,%5,%6,%7},{%8,%9},{%0,%1,%2,%3};"
                        : "+f"(c[mi][ni][0]), "+f"(c[mi][ni][1]),
                          "+f"(c[mi][ni][2]), "+f"(c[mi][ni][3])
                        : "r"(a[mi][0]), "r"(a[mi][1]), "r"(a[mi][2]), "r"(a[mi][3]),
                          "r"(b0), "r"(b1));
                }
            }
        }
        __syncthreads();
    }

    // -------- epilogue --------
#pragma unroll
    for (int mi = 0; mi < 2; mi++) {
#pragma unroll
        for (int half = 0; half < 2; half++) {
            int li = warp_m + mi * 16 + (lane >> 2) + half * 8;
            if (li < Mloc) {
                long ro;
                if (MODE == 0) {
                    ro = (long)(m0 + li) * N;
                } else if (MODE == 1) {
                    ro = (long)(rowbase + li) * N;
                } else {
                    int r = rowbase + li;
                    int p = order[r / SEQ];
                    int s = r % SEQ;
                    ro = ((long)p * SEQ + s) * N;
                }
#pragma unroll
                for (int ni = 0; ni < 8; ni++) {
                    int col = n0 + warp_n + ni * 8 + (lane & 3) * 2;
                    float v0 = c[mi][ni][half * 2 + 0];
                    float v1 = c[mi][ni][half * 2 + 1];
                    if (biasp) { v0 += biasp[col]; v1 += biasp[col + 1]; }
                    if (RELU)  { v0 = fmaxf(v0, 0.f); v1 = fmaxf(v1, 0.f); }
                    if (OUTBF) {
                        __nv_bfloat162 pk = __float22bfloat162_rn(make_float2(v0, v1));
                        *(__nv_bfloat162*)((bf16*)C + ro + col) = pk;
                    } else {
                        *(float2*)((float*)C + ro + col) = make_float2(v0, v1);
                    }
                }
            }
        }
    }
}

// ================= TF32 GEMM (QKV + out-proj; B row-major [N,K]) ==========
#define ASTRIDE   36
#define ABUF (128 * ASTRIDE)
#define SMEM_BYTES  (4 * ABUF * 4)    // 73728

template<bool RELU>
__global__ void __launch_bounds__(256, 2) tgemm(
    const float* __restrict__ A, const float* __restrict__ Bm,
    const float* __restrict__ bias, const float* __restrict__ resid,
    float* __restrict__ C, int M, int N, int K)
{
    extern __shared__ float sm[];
    float* As = sm;
    float* Bs = sm + 2 * ABUF;

    int m0 = blockIdx.y * 128;
    int n0 = blockIdx.x * 128;
    int tid = threadIdx.x, lane = tid & 31, w = tid >> 5;
    int warp_m = (w & 3) * 32;
    int warp_n = (w >> 2) * 64;

    float c[2][8][4];
#pragma unroll
    for (int i = 0; i < 2; i++)
#pragma unroll
        for (int j = 0; j < 8; j++)
#pragma unroll
            for (int q = 0; q < 4; q++) c[i][j][q] = 0.f;

    const int nChunks = K >> 5;

    auto copyA = [&](int k0, int buf) {
        float* dst = As + buf * ABUF;
#pragma unroll
        for (int i = 0; i < 4; i++) {
            int f = tid + i * 256;
            int row = f >> 3;
            int kq  = (f & 7) * 4;
            int gr = m0 + row;
            int sz = (gr < M) ? 16 : 0;
            const float* src = A + (long)(gr < M ? gr : 0) * K + k0 + kq;
            cp_async16(dst + row * ASTRIDE + kq, src, sz);
        }
    };
    auto copyB = [&](int k0, int buf) {
        float* dst = Bs + buf * ABUF;
#pragma unroll
        for (int i = 0; i < 4; i++) {
            int f = tid + i * 256;
            int row = f >> 3;
            int kq  = (f & 7) * 4;
            const float* src = Bm + (long)(n0 + row) * K + k0 + kq;
            cp_async16(dst + row * ASTRIDE + kq, src, 16);
        }
    };

    copyA(0, 0); copyB(0, 0);
    cp_commit();

    for (int ch = 0; ch < nChunks; ch++) {
        if (ch + 1 < nChunks) {
            copyA((ch + 1) << 5, (ch + 1) & 1);
            copyB((ch + 1) << 5, (ch + 1) & 1);
        }
        cp_commit();
        cp_wait1();
        __syncthreads();

        const float* Ab = As + (ch & 1) * ABUF;
        const float* Bb = Bs + (ch & 1) * ABUF;

#pragma unroll
        for (int kk = 0; kk < 32; kk += 8) {
            int kb = kk + (lane & 3);
            unsigned a[2][4];
#pragma unroll
            for (int mi = 0; mi < 2; mi++) {
                int r = warp_m + mi * 16 + (lane >> 2);
                a[mi][0] = cvt_tf32(Ab[r * ASTRIDE + kb]);
                a[mi][1] = cvt_tf32(Ab[(r + 8) * ASTRIDE + kb]);
                a[mi][2] = cvt_tf32(Ab[r * ASTRIDE + kb + 4]);
                a[mi][3] = cvt_tf32(Ab[(r + 8) * ASTRIDE + kb + 4]);
            }
#pragma unroll
            for (int ni = 0; ni < 8; ni++) {
                int n = warp_n + ni * 8 + (lane >> 2);
                unsigned b0 = cvt_tf32(Bb[n * ASTRIDE + kb]);
                unsigned b1 = cvt_tf32(Bb[n * ASTRIDE + kb + 4]);
#pragma unroll
                for (int mi = 0; mi < 2; mi++) {
                    asm volatile(
                        "mma.sync.aligned.m16n8k8.row.col.f32.tf32.tf32.f32 "
                        "{%0,%1,%2,%3},{%4,%5,%6,%7},{%8,%9},{%0,%1,%2,%3};"
                        : "+f"(c[mi][ni][0]), "+f"(c[mi][ni][1]),
                          "+f"(c[mi][ni][2]), "+f"(c[mi][ni][3])
                        : "r"(a[mi][0]), "r"(a[mi][1]), "r"(a[mi][2]), "r"(a[mi][3]),
                          "r"(b0), "r"(b1));
                }
            }
        }
        __syncthreads();
    }

#pragma unroll
    for (int mi = 0; mi < 2; mi++) {
#pragma unroll
        for (int half = 0; half < 2; half++) {
            int row = m0 + warp_m + mi * 16 + (lane >> 2) + half * 8;
            if (row < M) {
                long ro = (long)row * N;
#pragma unroll
                for (int ni = 0; ni < 8; ni++) {
                    int col = n0 + warp_n + ni * 8 + (lane & 3) * 2;
                    float v0 = c[mi][ni][half * 2 + 0];
                    float v1 = c[mi][ni][half * 2 + 1];
                    if (bias)  { v0 += bias[col]; v1 += bias[col + 1]; }
                    if (RELU)  { v0 = fmaxf(v0, 0.f); v1 = fmaxf(v1, 0.f); }
                    if (resid) { v0 += resid[ro + col]; v1 += resid[ro + col + 1]; }
                    *(float2*)(C + ro + col) = make_float2(v0, v1);
                }
            }
        }
    }
}

// ---------------- transpose + convert fp32 [R,C] -> bf16 [C,R] -------------
__global__ __launch_bounds__(256) void tconv_kernel(
    const float* __restrict__ in, bf16* __restrict__ out, int R, int C)
{
    __shared__ float tile[32][33];
    long zoff = (long)blockIdx.z * R * C;
    in += zoff; out += zoff;
    int tx = threadIdx.x & 31, ty = threadIdx.x >> 5;
    int c0 = blockIdx.x * 32, r0 = blockIdx.y * 32;
#pragma unroll
    for (int j = 0; j < 4; j++)
        tile[ty + j * 8][tx] = in[(long)(r0 + ty + j * 8) * C + c0 + tx];
    __syncthreads();
#pragma unroll
    for (int j = 0; j < 4; j++)
        out[(long)(c0 + ty + j * 8) * R + r0 + tx] =
            __float2bfloat16_rn(tile[tx][ty + j * 8]);
}

// ---------------- layernorm (optional dual fp32+bf16 output) --------------
__global__ __launch_bounds__(256) void ln_kernel(
    const float* __restrict__ x, const float* __restrict__ w,
    const float* __restrict__ bvec, float* __restrict__ y,
    bf16* __restrict__ yb)
{
    long t = blockIdx.x;
    const float* xr = x + t * DMODEL;
    float* yr = y + t * DMODEL;
    int tid = threadIdx.x;
    float v[4];
    float s = 0.f, s2 = 0.f;
#pragma unroll
    for (int i = 0; i < 4; i++) {
        v[i] = xr[tid + i * 256];
        s += v[i]; s2 += v[i] * v[i];
    }
#pragma unroll
    for (int o = 16; o; o >>= 1) {
        s  += __shfl_xor_sync(0xffffffffu, s, o);
        s2 += __shfl_xor_sync(0xffffffffu, s2, o);
    }
    __shared__ float rs[8], rs2[8];
    if ((tid & 31) == 0) { rs[tid >> 5] = s; rs2[tid >> 5] = s2; }
    __syncthreads();
    float ts = 0.f, ts2 = 0.f;
#pragma unroll
    for (int i = 0; i < 8; i++) { ts += rs[i]; ts2 += rs2[i]; }
    float mean = ts * (1.0f / DMODEL);
    float var  = ts2 * (1.0f / DMODEL) - mean * mean;
    float inv  = rsqrtf(var + 1e-5f);
#pragma unroll
    for (int i = 0; i < 4; i++) {
        int d = tid + i * 256;
        float o = (v[i] - mean) * inv * w[d] + bvec[d];
        yr[d] = o;
        if (yb) yb[t * DMODEL + d] = __float2bfloat16_rn(o);
    }
}

// ---------------- fused attention (one block per (b,h)) -------------------
__global__ __launch_bounds__(256) void attn_kernel(
    const float* __restrict__ qkv, float* __restrict__ ao)
{
    __shared__ float Ks[SEQ * 65];
    __shared__ float Vs[SEQ * 65];
    __shared__ float qb[8][64];
    __shared__ float pb[8][80];

    int bh = blockIdx.x;
    int b = bh >> 4, h = bh & 15;
    int tid = threadIdx.x, lane = tid & 31, wrp = tid >> 5;
    long tok0 = (long)b * SEQ;

    for (int idx = tid; idx < SEQ * 64; idx += 256) {
        int s = idx >> 6, d = idx & 63;
        long off = (tok0 + s) * QKVD + h * 64 + d;
        Ks[s * 65 + d] = qkv[off + DMODEL];
        Vs[s * 65 + d] = qkv[off + 2 * DMODEL];
    }
    __syncthreads();

    for (int s = wrp; s < SEQ; s += 8) {
        long qoff = (tok0 + s) * QKVD + h * 64;
        qb[wrp][lane]      = qkv[qoff + lane];
        qb[wrp][lane + 32] = qkv[qoff + lane + 32];
        __syncwarp();

        float e[3];
        float mx = -1e30f;
#pragma unroll
        for (int jj = 0; jj < 3; jj++) {
            int j = lane + jj * 32;
            float dot = -1e30f;
            if (j < SEQ) {
                const float* kr = Ks + j * 65;
                float a = 0.f;
#pragma unroll
                for (int d = 0; d < 64; d++) a += qb[wrp][d] * kr[d];
                dot = a * 0.125f;
            }
            e[jj] = dot;
            mx = fmaxf(mx, dot);
        }
#pragma unroll
        for (int o = 16; o; o >>= 1) mx = fmaxf(mx, __shfl_xor_sync(0xffffffffu, mx, o));

        float ssum = 0.f;
#pragma unroll
        for (int jj = 0; jj < 3; jj++) {
            int j = lane + jj * 32;
            float p = (j < SEQ) ? __expf(e[jj] - mx) : 0.f;
            e[jj] = p; ssum += p;
        }
#pragma unroll
        for (int o = 16; o; o >>= 1) ssum += __shfl_xor_sync(0xffffffffu, ssum, o);
        float inv = 1.0f / ssum;
#pragma unroll
        for (int jj = 0; jj < 3; jj++) {
            int j = lane + jj * 32;
            if (j < SEQ) pb[wrp][j] = e[jj] * inv;
        }
        __syncwarp();

        float a0 = 0.f, a1 = 0.f;
        for (int j = 0; j < SEQ; j++) {
            float p = pb[wrp][j];
            a0 += p * Vs[j * 65 + lane];
            a1 += p * Vs[j * 65 + lane + 32];
        }
        long orow = (tok0 + s) * DMODEL + h * 64;
        ao[orow + lane]      = a0;
        ao[orow + lane + 32] = a1;
        __syncwarp();
    }
}

// ---------------- router ----------------
__global__ __launch_bounds__(256) void router_kernel(
    const float* __restrict__ ffn, const float* __restrict__ rw,
    int* __restrict__ topi, float* __restrict__ gates)
{
    int b = blockIdx.x;
    const float* xr = ffn + (long)b * SEQ * DMODEL;
    int tid = threadIdx.x;
    int e = tid >> 5, lane = tid & 31;
    const float* wr = rw + e * DMODEL;
    float s = 0.f;
    for (int d = lane; d < DMODEL; d += 32) s += xr[d] * wr[d];
#pragma unroll
    for (int o = 16; o; o >>= 1) s += __shfl_xor_sync(0xffffffffu, s, o);
    __shared__ float lg[NEXP];
    if (lane == 0) lg[e] = s;
    __syncthreads();
    if (tid == 0) {
        int i0 = 0; float v0 = lg[0];
        for (int i = 1; i < NEXP; i++) if (lg[i] > v0) { v0 = lg[i]; i0 = i; }
        int i1 = -1; float v1 = -1e30f;
        for (int i = 0; i < NEXP; i++) if (i != i0 && lg[i] > v1) { v1 = lg[i]; i1 = i; }
        float e1 = __expf(v1 - v0);
        float den = 1.f + e1;
        topi[b * TOPK]     = i0;
        topi[b * TOPK + 1] = i1;
        gates[b * TOPK]     = 1.f / den;
        gates[b * TOPK + 1] = e1 / den;
    }
}

// ---------------- MoE routing setup: sort pairs by expert + tile table -----
__global__ void moe_setup(const int* __restrict__ topi,
                          int* __restrict__ order, int* __restrict__ tileE,
                          int* __restrict__ tileR, int* __restrict__ tileM,
                          int* __restrict__ ntiles)
{
    __shared__ int cnt[NEXP], off[NEXP];
    int tid = threadIdx.x;                  // 256 threads = 256 pairs
    if (tid < NEXP) cnt[tid] = 0;
    __syncthreads();
    int e = topi[tid];
    int pos = atomicAdd(&cnt[e], 1);
    __syncthreads();
    if (tid == 0) {
        int o = 0;
        for (int i = 0; i < NEXP; i++) { off[i] = o; o += cnt[i]; }
    }
    __syncthreads();
    order[off[e] + pos] = tid;
    if (tid == 0) {
        int t = 0, rowbase = 0;
        for (int e2 = 0; e2 < NEXP; e2++) {
            int rows = cnt[e2] * SEQ;
            int done = 0;
            while (done < rows) {
                int m = rows - done; if (m > 128) m = 128;
                tileE[t] = e2; tileR[t] = rowbase + done; tileM[t] = m;
                t++; done += 128;
            }
            rowbase += rows;
        }
        *ntiles = t;
    }
}

// ---------------- final combine ----------------
__global__ __launch_bounds__(256) void combine_kernel(
    const float* __restrict__ x, const float* __restrict__ sho,
    const float* __restrict__ eo, const float* __restrict__ gates,
    float* __restrict__ out)
{
    long t = blockIdx.x;
    int tid = threadIdx.x;
    int b = (int)(t / SEQ);
    int s = (int)(t - (long)b * SEQ);
    float g0 = gates[b * TOPK], g1 = gates[b * TOPK + 1];
    long base = t * DMODEL;
    long e0 = ((long)(b * TOPK) * SEQ + s) * DMODEL;
    long e1 = e0 + (long)SEQ * DMODEL;
#pragma unroll
    for (int i = 0; i < 4; i++) {
        int d = tid + i * 256;
        out[base + d] = x[base + d] + sho[base + d] + g0 * eo[e0 + d] + g1 * eo[e1 + d];
    }
}

// ---------------- launch ----------------
extern "C" void kernel_launch(void* const* d_in, const int* in_sizes, int n_in,
                              void* d_out, int out_size)
{
    const float* src   = (const float*)d_in[0];
    const float* pw    = (const float*)d_in[1];
    const float* pbias = (const float*)d_in[2];
    const float* ow    = (const float*)d_in[3];
    const float* ob    = (const float*)d_in[4];
    const float* ln1w  = (const float*)d_in[5];
    const float* ln1b  = (const float*)d_in[6];
    const float* ln2w  = (const float*)d_in[7];
    const float* ln2b  = (const float*)d_in[8];
    const float* rw    = (const float*)d_in[9];
    const float* ew1   = (const float*)d_in[10];
    const float* eb1   = (const float*)d_in[11];
    const float* ew2   = (const float*)d_in[12];
    const float* eb2   = (const float*)d_in[13];
    const float* sw1   = (const float*)d_in[14];
    const float* sb1   = (const float*)d_in[15];
    const float* sw2   = (const float*)d_in[16];
    const float* sb2   = (const float*)d_in[17];

    float *xn, *qkv, *ao, *x, *ffn, *eo, *sho, *gates;
    bf16 *ffnb, *hmoe, *hsh, *ew1t, *ew2t, *sw1t, *sw2t;
    int *topi, *order, *tileE, *tileR, *tileM, *ntiles;
    cudaGetSymbolAddress((void**)&xn,   g_xn);
    cudaGetSymbolAddress((void**)&qkv,  g_qkv);
    cudaGetSymbolAddress((void**)&ao,   g_ao);
    cudaGetSymbolAddress((void**)&x,    g_x);
    cudaGetSymbolAddress((void**)&ffn,  g_ffn);
    cudaGetSymbolAddress((void**)&ffnb, g_ffnb);
    cudaGetSymbolAddress((void**)&hmoe, g_hmoe);
    cudaGetSymbolAddress((void**)&eo,   g_eo);
    cudaGetSymbolAddress((void**)&hsh,  g_hsh);
    cudaGetSymbolAddress((void**)&sho,  g_sho);
    cudaGetSymbolAddress((void**)&topi, g_topi);
    cudaGetSymbolAddress((void**)&gates,g_gates);
    cudaGetSymbolAddress((void**)&order,g_order);
    cudaGetSymbolAddress((void**)&tileE,g_tileE);
    cudaGetSymbolAddress((void**)&tileR,g_tileR);
    cudaGetSymbolAddress((void**)&tileM,g_tileM);
    cudaGetSymbolAddress((void**)&ntiles,g_ntiles);
    cudaGetSymbolAddress((void**)&ew1t, g_ew1t);
    cudaGetSymbolAddress((void**)&ew2t, g_ew2t);
    cudaGetSymbolAddress((void**)&sw1t, g_sw1t);
    cudaGetSymbolAddress((void**)&sw2t, g_sw2t);

    cudaFuncSetAttribute(tgemm<false>, cudaFuncAttributeMaxDynamicSharedMemorySize, SMEM_BYTES);
    cudaFuncSetAttribute(bgemm<0, true,  true >, cudaFuncAttributeMaxDynamicSharedMemorySize, BGSMEM);
    cudaFuncSetAttribute(bgemm<0, false, false>, cudaFuncAttributeMaxDynamicSharedMemorySize, BGSMEM);
    cudaFuncSetAttribute(bgemm<1, true,  true >, cudaFuncAttributeMaxDynamicSharedMemorySize, BGSMEM);
    cudaFuncSetAttribute(bgemm<2, false, false>, cudaFuncAttributeMaxDynamicSharedMemorySize, BGSMEM);

    const int mt_tok = TOK / 128;   // 77 (exact)

    // 0. weight convert+transpose
    tconv_kernel<<<dim3(FF / 32, DMODEL / 32, NEXP), 256>>>(ew1, ew1t, DMODEL, FF);
    tconv_kernel<<<dim3(DMODEL / 32, FF / 32, NEXP), 256>>>(ew2, ew2t, FF, DMODEL);
    tconv_kernel<<<dim3(FF / 32, DMODEL / 32, 1),    256>>>(sw1, sw1t, DMODEL, FF);
    tconv_kernel<<<dim3(DMODEL / 32, FF / 32, 1),    256>>>(sw2, sw2t, FF, DMODEL);

    // 1. LN1
    ln_kernel<<<TOK, 256>>>(src, ln1w, ln1b, xn, nullptr);
    // 2. QKV (TF32)
    tgemm<false><<<dim3(QKVD / 128, mt_tok, 1), 256, SMEM_BYTES>>>(
        xn, pw, pbias, nullptr, qkv, TOK, QKVD, DMODEL);
    // 3. attention
    attn_kernel<<<NB * NHEAD, 256>>>(qkv, ao);
    // 4. x = src + ao @ out_w^T + out_b  (TF32)
    tgemm<false><<<dim3(DMODEL / 128, mt_tok, 1), 256, SMEM_BYTES>>>(
        ao, ow, ob, src, x, TOK, DMODEL, DMODEL);
    // 5. LN2 -> fp32 + bf16
    ln_kernel<<<TOK, 256>>>(x, ln2w, ln2b, ffn, ffnb);
    // 6. router top-2 + routing tables
    router_kernel<<<NB, 256>>>(ffn, rw, topi, gates);
    moe_setup<<<1, 256>>>(topi, order, tileE, tileR, tileM, ntiles);
    // 7. MoE layer 1 (gather A, sorted C, bf16 out)
    bgemm<1, true, true><<<dim3(FF / 128, MAXT), 256, BGSMEM>>>(
        ffnb, ew1t, eb1, hmoe, 0, FF, DMODEL, order, tileE, tileR, tileM, ntiles);
    // 8. MoE layer 2 (contiguous A, scatter C to pair-indexed eo, fp32 out)
    bgemm<2, false, false><<<dim3(DMODEL / 128, MAXT), 256, BGSMEM>>>(
        hmoe, ew2t, eb2, eo, 0, DMODEL, FF, order, tileE, tileR, tileM, ntiles);
    // 9. shared layer 1
    bgemm<0, true, true><<<dim3(FF / 128, mt_tok), 256, BGSMEM>>>(
        ffnb, sw1t, sb1, hsh, TOK, FF, DMODEL, nullptr, nullptr, nullptr, nullptr, nullptr);
    // 10. shared layer 2
    bgemm<0, false, false><<<dim3(DMODEL / 128, mt_tok), 256, BGSMEM>>>(
        hsh, sw2t, sb2, sho, TOK, DMODEL, FF, nullptr, nullptr, nullptr, nullptr, nullptr);
    // 11. out = x + moe + shared
    combine_kernel<<<TOK, 256>>>(x, sho, eo, gates, (float*)d_out);
}

// round 6
// speedup vs baseline: 7.4898x; 1.0774x over previous
#include <cuda_runtime.h>
#include <cuda_bf16.h>

// ---------------- problem constants ----------------
#define NB      128
#define SEQ     77
#define DMODEL  1024
#define NHEAD   16
#define FF      4096
#define NEXP    8
#define TOPK    2
#define TOK     (NB * SEQ)          // 9856
#define QKVD    (3 * DMODEL)        // 3072
#define NPAIR   (NB * TOPK)         // 256
#define TOTROWS (NPAIR * SEQ)       // 19712
#define MAXT    162                 // max single-expert M-tiles

typedef __nv_bfloat16 bf16;

// ---------------- scratch (device globals; no allocation) ----------------
__device__ float g_xn  [(size_t)TOK * DMODEL];
__device__ float g_qkv [(size_t)TOK * QKVD];
__device__ float g_ao  [(size_t)TOK * DMODEL];
__device__ float g_x   [(size_t)TOK * DMODEL];
__device__ float g_ffn [(size_t)TOK * DMODEL];
__device__ bf16  g_ffnb[(size_t)TOK * DMODEL];
__device__ bf16  g_hmoe[(size_t)TOTROWS * FF];      // expert-sorted rows
__device__ float g_eo  [(size_t)TOTROWS * DMODEL];  // pair-indexed
__device__ bf16  g_hsh [(size_t)TOK * FF];
__device__ float g_sho [(size_t)TOK * DMODEL];
__device__ int   g_topi [NPAIR];
__device__ float g_gates[NPAIR];
// routing/tiling tables
__device__ int g_order[NPAIR];
__device__ int g_tileE[MAXT];
__device__ int g_tileR[MAXT];
__device__ int g_tileM[MAXT];
__device__ int g_ntiles;
// transposed bf16 weights
__device__ bf16 g_ew1t[(size_t)NEXP * FF * DMODEL];
__device__ bf16 g_ew2t[(size_t)NEXP * DMODEL * FF];
__device__ bf16 g_sw1t[(size_t)FF * DMODEL];
__device__ bf16 g_sw2t[(size_t)DMODEL * FF];

// ---------------- helpers ----------------
__device__ __forceinline__ unsigned cvt_tf32(float x) {
    unsigned r;
    asm("cvt.rna.tf32.f32 %0, %1;" : "=r"(r) : "f"(x));
    return r;
}
__device__ __forceinline__ void cp_async16(void* dst, const void* src, int sz) {
    unsigned saddr = (unsigned)__cvta_generic_to_shared(dst);
    asm volatile("cp.async.cg.shared.global [%0], [%1], 16, %2;\n"
                 :: "r"(saddr), "l"(src), "r"(sz));
}
__device__ __forceinline__ void cp_commit() {
    asm volatile("cp.async.commit_group;\n");
}
__device__ __forceinline__ void cp_wait1() {
    asm volatile("cp.async.wait_group 1;\n");
}
__device__ __forceinline__ void cp_wait2() {
    asm volatile("cp.async.wait_group 2;\n");
}
__device__ __forceinline__ void ldsm4(unsigned& r0, unsigned& r1,
                                      unsigned& r2, unsigned& r3, unsigned addr) {
    asm volatile("ldmatrix.sync.aligned.m8n8.x4.shared.b16 {%0,%1,%2,%3}, [%4];"
                 : "=r"(r0), "=r"(r1), "=r"(r2), "=r"(r3) : "r"(addr));
}

// ================= bf16 tensor-core GEMM =================
// MODE 0: plain          A rows m0+i,                 C rows m0+i
// MODE 1: MoE layer 1    A rows gathered via order[], C rows sorted (rowbase+i)
// MODE 2: MoE layer 2    A rows sorted (contiguous),  C rows scattered via order[]
// B always pre-transposed bf16 [N][K]; expert weights selected by tile table.
#define AS 40                     // smem k-pitch in bf16 (80B): conflict-free
#define TBUF (128 * AS)           // 5120 bf16 per tile buffer
#define BGSMEM (6 * TBUF * (int)sizeof(bf16))   // 61440 B (3-stage A+B)

template<int MODE, bool RELU, bool OUTBF>
__global__ void __launch_bounds__(256, 2) bgemm(
    const bf16* __restrict__ A, const bf16* __restrict__ Bm,
    const float* __restrict__ bias, void* __restrict__ C,
    int M, int N, int K,
    const int* __restrict__ order, const int* __restrict__ tileE,
    const int* __restrict__ tileR, const int* __restrict__ tileM,
    const int* __restrict__ ntiles)
{
    extern __shared__ bf16 sh[];

    int ty = blockIdx.y;
    int expert = 0, rowbase = 0, Mloc = 128, m0 = 0;
    if (MODE == 0) {
        m0 = ty * 128;
        Mloc = M - m0; if (Mloc > 128) Mloc = 128;
    } else {
        if (ty >= *ntiles) return;
        expert  = tileE[ty];
        rowbase = tileR[ty];
        Mloc    = tileM[ty];
    }
    const bf16* Bp = Bm + (long)expert * N * K;
    const float* biasp = bias ? (bias + (long)expert * N) : nullptr;

    int n0 = blockIdx.x * 128;
    int tid = threadIdx.x, lane = tid & 31, w = tid >> 5;
    int warp_m = (w & 3) * 32;
    int warp_n = (w >> 2) * 64;

    // ---- precompute per-thread load row pointers ----
    int i0 = tid >> 2;              // 0..63
    int kq = (tid & 3) * 8;         // bf16 offset 0,8,16,24
    const bf16* arow[2]; int asz[2];
    const bf16* brow[2];
#pragma unroll
    for (int j = 0; j < 2; j++) {
        int i = i0 + j * 64;
        bool valid = i < Mloc;
        asz[j] = valid ? 16 : 0;
        if (MODE == 0) {
            int gr = m0 + i;
            arow[j] = A + (long)(valid ? gr : 0) * K;
        } else if (MODE == 1) {
            int r = rowbase + i;
            int rc = r < TOTROWS ? r : TOTROWS - 1;
            int p = order[rc / SEQ];
            int s = rc % SEQ;
            int b = p / TOPK;
            arow[j] = A + ((long)b * SEQ + s) * K;
        } else {
            int r = rowbase + i;
            arow[j] = A + (long)(valid ? r : 0) * K;
        }
        brow[j] = Bp + (long)(n0 + i) * K;
    }

    // ---- ldmatrix per-lane smem byte offsets (within one buffer, kk=0) ----
    unsigned smem_u32 = (unsigned)__cvta_generic_to_shared(sh);
    unsigned aOff[2], bOff[4];
    {
        int la = lane & 15, ha = lane >> 4;            // A: rows, k-half
        int nb = (lane & 7) + ((lane >> 4) & 1) * 8;   // B: n within 16
        int kb = ((lane >> 3) & 1) * 8;                // B: k-half
#pragma unroll
        for (int mi = 0; mi < 2; mi++)
            aOff[mi] = ((warp_m + mi * 16 + la) * AS + ha * 8) * 2;
#pragma unroll
        for (int nj = 0; nj < 4; nj++)
            bOff[nj] = ((warp_n + nj * 16 + nb) * AS + kb) * 2;
    }

    float c[2][8][4];
#pragma unroll
    for (int i = 0; i < 2; i++)
#pragma unroll
        for (int j = 0; j < 8; j++)
#pragma unroll
            for (int q = 0; q < 4; q++) c[i][j][q] = 0.f;

    const int nChunks = K >> 5;

    auto loadChunk = [&](int k0, int buf) {
        bf16* Ad = sh + buf * TBUF;
        bf16* Bd = sh + (3 + buf) * TBUF;
#pragma unroll
        for (int j = 0; j < 2; j++) {
            int i = i0 + j * 64;
            cp_async16(Ad + i * AS + kq, arow[j] + k0 + kq, asz[j]);
            cp_async16(Bd + i * AS + kq, brow[j] + k0 + kq, 16);
        }
    };

    loadChunk(0, 0); cp_commit();
    if (nChunks > 1) loadChunk(32, 1);
    cp_commit();

    for (int ch = 0; ch < nChunks; ch++) {
        if (ch + 2 < nChunks) loadChunk((ch + 2) << 5, (ch + 2) % 3);
        cp_commit();
        cp_wait2();
        __syncthreads();

        int buf = ch % 3;
        unsigned Abase = smem_u32 + buf * (TBUF * 2);
        unsigned Bbase = smem_u32 + (3 + buf) * (TBUF * 2);

#pragma unroll
        for (int kk = 0; kk < 32; kk += 16) {
            unsigned kByte = kk * 2;
            unsigned a[2][4];
#pragma unroll
            for (int mi = 0; mi < 2; mi++)
                ldsm4(a[mi][0], a[mi][1], a[mi][2], a[mi][3],
                      Abase + aOff[mi] + kByte);
#pragma unroll
            for (int nj = 0; nj < 4; nj++) {
                unsigned b0, b1, b2, b3;
                ldsm4(b0, b1, b2, b3, Bbase + bOff[nj] + kByte);
#pragma unroll
                for (int mi = 0; mi < 2; mi++) {
                    asm volatile(
                        "mma.sync.aligned.m16n8k16.row.col.f32.bf16.bf16.f32 "
                        "{%0,%1,%2,%3},{%4,%5,%6,%7},{%8,%9},{%0,%1,%2,%3};"
                        : "+f"(c[mi][nj * 2][0]), "+f"(c[mi][nj * 2][1]),
                          "+f"(c[mi][nj * 2][2]), "+f"(c[mi][nj * 2][3])
                        : "r"(a[mi][0]), "r"(a[mi][1]), "r"(a[mi][2]), "r"(a[mi][3]),
                          "r"(b0), "r"(b1));
                    asm volatile(
                        "mma.sync.aligned.m16n8k16.row.col.f32.bf16.bf16.f32 "
                        "{%0,%1,%2,%3},{%4,%5,%6,%7},{%8,%9},{%0,%1,%2,%3};"
                        : "+f"(c[mi][nj * 2 + 1][0]), "+f"(c[mi][nj * 2 + 1][1]),
                          "+f"(c[mi][nj * 2 + 1][2]), "+f"(c[mi][nj * 2 + 1][3])
                        : "r"(a[mi][0]), "r"(a[mi][1]), "r"(a[mi][2]), "r"(a[mi][3]),
                          "r"(b2), "r"(b3));
                }
            }
        }
        __syncthreads();
    }

    // -------- epilogue --------
#pragma unroll
    for (int mi = 0; mi < 2; mi++) {
#pragma unroll
        for (int half = 0; half < 2; half++) {
            int li = warp_m + mi * 16 + (lane >> 2) + half * 8;
            if (li < Mloc) {
                long ro;
                if (MODE == 0) {
                    ro = (long)(m0 + li) * N;
                } else if (MODE == 1) {
                    ro = (long)(rowbase + li) * N;
                } else {
                    int r = rowbase + li;
                    int p = order[r / SEQ];
                    int s = r % SEQ;
                    ro = ((long)p * SEQ + s) * N;
                }
#pragma unroll
                for (int ni = 0; ni < 8; ni++) {
                    int col = n0 + warp_n + ni * 8 + (lane & 3) * 2;
                    float v0 = c[mi][ni][half * 2 + 0];
                    float v1 = c[mi][ni][half * 2 + 1];
                    if (biasp) { v0 += biasp[col]; v1 += biasp[col + 1]; }
                    if (RELU)  { v0 = fmaxf(v0, 0.f); v1 = fmaxf(v1, 0.f); }
                    if (OUTBF) {
                        __nv_bfloat162 pk = __float22bfloat162_rn(make_float2(v0, v1));
                        *(__nv_bfloat162*)((bf16*)C + ro + col) = pk;
                    } else {
                        *(float2*)((float*)C + ro + col) = make_float2(v0, v1);
                    }
                }
            }
        }
    }
}

// ================= TF32 GEMM (QKV + out-proj; B row-major [N,K]) ==========
#define ASTRIDE   36
#define ABUF (128 * ASTRIDE)
#define SMEM_BYTES  (4 * ABUF * 4)    // 73728

template<bool RELU>
__global__ void __launch_bounds__(256, 2) tgemm(
    const float* __restrict__ A, const float* __restrict__ Bm,
    const float* __restrict__ bias, const float* __restrict__ resid,
    float* __restrict__ C, int M, int N, int K)
{
    extern __shared__ float sm[];
    float* As = sm;
    float* Bs = sm + 2 * ABUF;

    int m0 = blockIdx.y * 128;
    int n0 = blockIdx.x * 128;
    int tid = threadIdx.x, lane = tid & 31, w = tid >> 5;
    int warp_m = (w & 3) * 32;
    int warp_n = (w >> 2) * 64;

    float c[2][8][4];
#pragma unroll
    for (int i = 0; i < 2; i++)
#pragma unroll
        for (int j = 0; j < 8; j++)
#pragma unroll
            for (int q = 0; q < 4; q++) c[i][j][q] = 0.f;

    const int nChunks = K >> 5;

    auto copyA = [&](int k0, int buf) {
        float* dst = As + buf * ABUF;
#pragma unroll
        for (int i = 0; i < 4; i++) {
            int f = tid + i * 256;
            int row = f >> 3;
            int kq  = (f & 7) * 4;
            int gr = m0 + row;
            int sz = (gr < M) ? 16 : 0;
            const float* src = A + (long)(gr < M ? gr : 0) * K + k0 + kq;
            cp_async16(dst + row * ASTRIDE + kq, src, sz);
        }
    };
    auto copyB = [&](int k0, int buf) {
        float* dst = Bs + buf * ABUF;
#pragma unroll
        for (int i = 0; i < 4; i++) {
            int f = tid + i * 256;
            int row = f >> 3;
            int kq  = (f & 7) * 4;
            const float* src = Bm + (long)(n0 + row) * K + k0 + kq;
            cp_async16(dst + row * ASTRIDE + kq, src, 16);
        }
    };

    copyA(0, 0); copyB(0, 0);
    cp_commit();

    for (int ch = 0; ch < nChunks; ch++) {
        if (ch + 1 < nChunks) {
            copyA((ch + 1) << 5, (ch + 1) & 1);
            copyB((ch + 1) << 5, (ch + 1) & 1);
        }
        cp_commit();
        cp_wait1();
        __syncthreads();

        const float* Ab = As + (ch & 1) * ABUF;
        const float* Bb = Bs + (ch & 1) * ABUF;

#pragma unroll
        for (int kk = 0; kk < 32; kk += 8) {
            int kb = kk + (lane & 3);
            unsigned a[2][4];
#pragma unroll
            for (int mi = 0; mi < 2; mi++) {
                int r = warp_m + mi * 16 + (lane >> 2);
                a[mi][0] = cvt_tf32(Ab[r * ASTRIDE + kb]);
                a[mi][1] = cvt_tf32(Ab[(r + 8) * ASTRIDE + kb]);
                a[mi][2] = cvt_tf32(Ab[r * ASTRIDE + kb + 4]);
                a[mi][3] = cvt_tf32(Ab[(r + 8) * ASTRIDE + kb + 4]);
            }
#pragma unroll
            for (int ni = 0; ni < 8; ni++) {
                int n = warp_n + ni * 8 + (lane >> 2);
                unsigned b0 = cvt_tf32(Bb[n * ASTRIDE + kb]);
                unsigned b1 = cvt_tf32(Bb[n * ASTRIDE + kb + 4]);
#pragma unroll
                for (int mi = 0; mi < 2; mi++) {
                    asm volatile(
                        "mma.sync.aligned.m16n8k8.row.col.f32.tf32.tf32.f32 "
                        "{%0,%1,%2,%3},{%4,%5,%6,%7},{%8,%9},{%0,%1,%2,%3};"
                        : "+f"(c[mi][ni][0]), "+f"(c[mi][ni][1]),
                          "+f"(c[mi][ni][2]), "+f"(c[mi][ni][3])
                        : "r"(a[mi][0]), "r"(a[mi][1]), "r"(a[mi][2]), "r"(a[mi][3]),
                          "r"(b0), "r"(b1));
                }
            }
        }
        __syncthreads();
    }

#pragma unroll
    for (int mi = 0; mi < 2; mi++) {
#pragma unroll
        for (int half = 0; half < 2; half++) {
            int row = m0 + warp_m + mi * 16 + (lane >> 2) + half * 8;
            if (row < M) {
                long ro = (long)row * N;
#pragma unroll
                for (int ni = 0; ni < 8; ni++) {
                    int col = n0 + warp_n + ni * 8 + (lane & 3) * 2;
                    float v0 = c[mi][ni][half * 2 + 0];
                    float v1 = c[mi][ni][half * 2 + 1];
                    if (bias)  { v0 += bias[col]; v1 += bias[col + 1]; }
                    if (RELU)  { v0 = fmaxf(v0, 0.f); v1 = fmaxf(v1, 0.f); }
                    if (resid) { v0 += resid[ro + col]; v1 += resid[ro + col + 1]; }
                    *(float2*)(C + ro + col) = make_float2(v0, v1);
                }
            }
        }
    }
}

// ---------------- transpose + convert fp32 [R,C] -> bf16 [C,R] -------------
__global__ __launch_bounds__(256) void tconv_kernel(
    const float* __restrict__ in, bf16* __restrict__ out, int R, int C)
{
    __shared__ float tile[32][33];
    long zoff = (long)blockIdx.z * R * C;
    in += zoff; out += zoff;
    int tx = threadIdx.x & 31, ty = threadIdx.x >> 5;
    int c0 = blockIdx.x * 32, r0 = blockIdx.y * 32;
#pragma unroll
    for (int j = 0; j < 4; j++)
        tile[ty + j * 8][tx] = in[(long)(r0 + ty + j * 8) * C + c0 + tx];
    __syncthreads();
#pragma unroll
    for (int j = 0; j < 4; j++)
        out[(long)(c0 + ty + j * 8) * R + r0 + tx] =
            __float2bfloat16_rn(tile[tx][ty + j * 8]);
}

// ---------------- layernorm (optional dual fp32+bf16 output) --------------
__global__ __launch_bounds__(256) void ln_kernel(
    const float* __restrict__ x, const float* __restrict__ w,
    const float* __restrict__ bvec, float* __restrict__ y,
    bf16* __restrict__ yb)
{
    long t = blockIdx.x;
    const float* xr = x + t * DMODEL;
    float* yr = y + t * DMODEL;
    int tid = threadIdx.x;
    float v[4];
    float s = 0.f, s2 = 0.f;
#pragma unroll
    for (int i = 0; i < 4; i++) {
        v[i] = xr[tid + i * 256];
        s += v[i]; s2 += v[i] * v[i];
    }
#pragma unroll
    for (int o = 16; o; o >>= 1) {
        s  += __shfl_xor_sync(0xffffffffu, s, o);
        s2 += __shfl_xor_sync(0xffffffffu, s2, o);
    }
    __shared__ float rs[8], rs2[8];
    if ((tid & 31) == 0) { rs[tid >> 5] = s; rs2[tid >> 5] = s2; }
    __syncthreads();
    float ts = 0.f, ts2 = 0.f;
#pragma unroll
    for (int i = 0; i < 8; i++) { ts += rs[i]; ts2 += rs2[i]; }
    float mean = ts * (1.0f / DMODEL);
    float var  = ts2 * (1.0f / DMODEL) - mean * mean;
    float inv  = rsqrtf(var + 1e-5f);
#pragma unroll
    for (int i = 0; i < 4; i++) {
        int d = tid + i * 256;
        float o = (v[i] - mean) * inv * w[d] + bvec[d];
        yr[d] = o;
        if (yb) yb[t * DMODEL + d] = __float2bfloat16_rn(o);
    }
}

// ---------------- fused attention (one block per (b,h)) -------------------
__global__ __launch_bounds__(256) void attn_kernel(
    const float* __restrict__ qkv, float* __restrict__ ao)
{
    __shared__ float Ks[SEQ * 65];
    __shared__ float Vs[SEQ * 65];
    __shared__ float qb[8][64];
    __shared__ float pb[8][80];

    int bh = blockIdx.x;
    int b = bh >> 4, h = bh & 15;
    int tid = threadIdx.x, lane = tid & 31, wrp = tid >> 5;
    long tok0 = (long)b * SEQ;

    for (int idx = tid; idx < SEQ * 64; idx += 256) {
        int s = idx >> 6, d = idx & 63;
        long off = (tok0 + s) * QKVD + h * 64 + d;
        Ks[s * 65 + d] = qkv[off + DMODEL];
        Vs[s * 65 + d] = qkv[off + 2 * DMODEL];
    }
    __syncthreads();

    for (int s = wrp; s < SEQ; s += 8) {
        long qoff = (tok0 + s) * QKVD + h * 64;
        qb[wrp][lane]      = qkv[qoff + lane];
        qb[wrp][lane + 32] = qkv[qoff + lane + 32];
        __syncwarp();

        float e[3];
        float mx = -1e30f;
#pragma unroll
        for (int jj = 0; jj < 3; jj++) {
            int j = lane + jj * 32;
            float dot = -1e30f;
            if (j < SEQ) {
                const float* kr = Ks + j * 65;
                float a = 0.f;
#pragma unroll
                for (int d = 0; d < 64; d++) a += qb[wrp][d] * kr[d];
                dot = a * 0.125f;
            }
            e[jj] = dot;
            mx = fmaxf(mx, dot);
        }
#pragma unroll
        for (int o = 16; o; o >>= 1) mx = fmaxf(mx, __shfl_xor_sync(0xffffffffu, mx, o));

        float ssum = 0.f;
#pragma unroll
        for (int jj = 0; jj < 3; jj++) {
            int j = lane + jj * 32;
            float p = (j < SEQ) ? __expf(e[jj] - mx) : 0.f;
            e[jj] = p; ssum += p;
        }
#pragma unroll
        for (int o = 16; o; o >>= 1) ssum += __shfl_xor_sync(0xffffffffu, ssum, o);
        float inv = 1.0f / ssum;
#pragma unroll
        for (int jj = 0; jj < 3; jj++) {
            int j = lane + jj * 32;
            if (j < SEQ) pb[wrp][j] = e[jj] * inv;
        }
        __syncwarp();

        float a0 = 0.f, a1 = 0.f;
        for (int j = 0; j < SEQ; j++) {
            float p = pb[wrp][j];
            a0 += p * Vs[j * 65 + lane];
            a1 += p * Vs[j * 65 + lane + 32];
        }
        long orow = (tok0 + s) * DMODEL + h * 64;
        ao[orow + lane]      = a0;
        ao[orow + lane + 32] = a1;
        __syncwarp();
    }
}

// ---------------- router ----------------
__global__ __launch_bounds__(256) void router_kernel(
    const float* __restrict__ ffn, const float* __restrict__ rw,
    int* __restrict__ topi, float* __restrict__ gates)
{
    int b = blockIdx.x;
    const float* xr = ffn + (long)b * SEQ * DMODEL;
    int tid = threadIdx.x;
    int e = tid >> 5, lane = tid & 31;
    const float* wr = rw + e * DMODEL;
    float s = 0.f;
    for (int d = lane; d < DMODEL; d += 32) s += xr[d] * wr[d];
#pragma unroll
    for (int o = 16; o; o >>= 1) s += __shfl_xor_sync(0xffffffffu, s, o);
    __shared__ float lg[NEXP];
    if (lane == 0) lg[e] = s;
    __syncthreads();
    if (tid == 0) {
        int i0 = 0; float v0 = lg[0];
        for (int i = 1; i < NEXP; i++) if (lg[i] > v0) { v0 = lg[i]; i0 = i; }
        int i1 = -1; float v1 = -1e30f;
        for (int i = 0; i < NEXP; i++) if (i != i0 && lg[i] > v1) { v1 = lg[i]; i1 = i; }
        float e1 = __expf(v1 - v0);
        float den = 1.f + e1;
        topi[b * TOPK]     = i0;
        topi[b * TOPK + 1] = i1;
        gates[b * TOPK]     = 1.f / den;
        gates[b * TOPK + 1] = e1 / den;
    }
}

// ---------------- MoE routing setup: sort pairs by expert + tile table -----
__global__ void moe_setup(const int* __restrict__ topi,
                          int* __restrict__ order, int* __restrict__ tileE,
                          int* __restrict__ tileR, int* __restrict__ tileM,
                          int* __restrict__ ntiles)
{
    __shared__ int cnt[NEXP], off[NEXP];
    int tid = threadIdx.x;
    if (tid < NEXP) cnt[tid] = 0;
    __syncthreads();
    int e = topi[tid];
    int pos = atomicAdd(&cnt[e], 1);
    __syncthreads();
    if (tid == 0) {
        int o = 0;
        for (int i = 0; i < NEXP; i++) { off[i] = o; o += cnt[i]; }
    }
    __syncthreads();
    order[off[e] + pos] = tid;
    if (tid == 0) {
        int t = 0, rowbase = 0;
        for (int e2 = 0; e2 < NEXP; e2++) {
            int rows = cnt[e2] * SEQ;
            int done = 0;
            while (done < rows) {
                int m = rows - done; if (m > 128) m = 128;
                tileE[t] = e2; tileR[t] = rowbase + done; tileM[t] = m;
                t++; done += 128;
            }
            rowbase += rows;
        }
        *ntiles = t;
    }
}

// ---------------- final combine ----------------
__global__ __launch_bounds__(256) void combine_kernel(
    const float* __restrict__ x, const float* __restrict__ sho,
    const float* __restrict__ eo, const float* __restrict__ gates,
    float* __restrict__ out)
{
    long t = blockIdx.x;
    int tid = threadIdx.x;
    int b = (int)(t / SEQ);
    int s = (int)(t - (long)b * SEQ);
    float g0 = gates[b * TOPK], g1 = gates[b * TOPK + 1];
    long base = t * DMODEL;
    long e0 = ((long)(b * TOPK) * SEQ + s) * DMODEL;
    long e1 = e0 + (long)SEQ * DMODEL;
#pragma unroll
    for (int i = 0; i < 4; i++) {
        int d = tid + i * 256;
        out[base + d] = x[base + d] + sho[base + d] + g0 * eo[e0 + d] + g1 * eo[e1 + d];
    }
}

// ---------------- launch ----------------
extern "C" void kernel_launch(void* const* d_in, const int* in_sizes, int n_in,
                              void* d_out, int out_size)
{
    const float* src   = (const float*)d_in[0];
    const float* pw    = (const float*)d_in[1];
    const float* pbias = (const float*)d_in[2];
    const float* ow    = (const float*)d_in[3];
    const float* ob    = (const float*)d_in[4];
    const float* ln1w  = (const float*)d_in[5];
    const float* ln1b  = (const float*)d_in[6];
    const float* ln2w  = (const float*)d_in[7];
    const float* ln2b  = (const float*)d_in[8];
    const float* rw    = (const float*)d_in[9];
    const float* ew1   = (const float*)d_in[10];
    const float* eb1   = (const float*)d_in[11];
    const float* ew2   = (const float*)d_in[12];
    const float* eb2   = (const float*)d_in[13];
    const float* sw1   = (const float*)d_in[14];
    const float* sb1   = (const float*)d_in[15];
    const float* sw2   = (const float*)d_in[16];
    const float* sb2   = (const float*)d_in[17];

    float *xn, *qkv, *ao, *x, *ffn, *eo, *sho, *gates;
    bf16 *ffnb, *hmoe, *hsh, *ew1t, *ew2t, *sw1t, *sw2t;
    int *topi, *order, *tileE, *tileR, *tileM, *ntiles;
    cudaGetSymbolAddress((void**)&xn,   g_xn);
    cudaGetSymbolAddress((void**)&qkv,  g_qkv);
    cudaGetSymbolAddress((void**)&ao,   g_ao);
    cudaGetSymbolAddress((void**)&x,    g_x);
    cudaGetSymbolAddress((void**)&ffn,  g_ffn);
    cudaGetSymbolAddress((void**)&ffnb, g_ffnb);
    cudaGetSymbolAddress((void**)&hmoe, g_hmoe);
    cudaGetSymbolAddress((void**)&eo,   g_eo);
    cudaGetSymbolAddress((void**)&hsh,  g_hsh);
    cudaGetSymbolAddress((void**)&sho,  g_sho);
    cudaGetSymbolAddress((void**)&topi, g_topi);
    cudaGetSymbolAddress((void**)&gates,g_gates);
    cudaGetSymbolAddress((void**)&order,g_order);
    cudaGetSymbolAddress((void**)&tileE,g_tileE);
    cudaGetSymbolAddress((void**)&tileR,g_tileR);
    cudaGetSymbolAddress((void**)&tileM,g_tileM);
    cudaGetSymbolAddress((void**)&ntiles,g_ntiles);
    cudaGetSymbolAddress((void**)&ew1t, g_ew1t);
    cudaGetSymbolAddress((void**)&ew2t, g_ew2t);
    cudaGetSymbolAddress((void**)&sw1t, g_sw1t);
    cudaGetSymbolAddress((void**)&sw2t, g_sw2t);

    cudaFuncSetAttribute(tgemm<false>, cudaFuncAttributeMaxDynamicSharedMemorySize, SMEM_BYTES);
    cudaFuncSetAttribute(bgemm<0, true,  true >, cudaFuncAttributeMaxDynamicSharedMemorySize, BGSMEM);
    cudaFuncSetAttribute(bgemm<0, false, false>, cudaFuncAttributeMaxDynamicSharedMemorySize, BGSMEM);
    cudaFuncSetAttribute(bgemm<1, true,  true >, cudaFuncAttributeMaxDynamicSharedMemorySize, BGSMEM);
    cudaFuncSetAttribute(bgemm<2, false, false>, cudaFuncAttributeMaxDynamicSharedMemorySize, BGSMEM);

    const int mt_tok = TOK / 128;   // 77 (exact)

    // 0. weight convert+transpose
    tconv_kernel<<<dim3(FF / 32, DMODEL / 32, NEXP), 256>>>(ew1, ew1t, DMODEL, FF);
    tconv_kernel<<<dim3(DMODEL / 32, FF / 32, NEXP), 256>>>(ew2, ew2t, FF, DMODEL);
    tconv_kernel<<<dim3(FF / 32, DMODEL / 32, 1),    256>>>(sw1, sw1t, DMODEL, FF);
    tconv_kernel<<<dim3(DMODEL / 32, FF / 32, 1),    256>>>(sw2, sw2t, FF, DMODEL);

    // 1. LN1
    ln_kernel<<<TOK, 256>>>(src, ln1w, ln1b, xn, nullptr);
    // 2. QKV (TF32)
    tgemm<false><<<dim3(QKVD / 128, mt_tok, 1), 256, SMEM_BYTES>>>(
        xn, pw, pbias, nullptr, qkv, TOK, QKVD, DMODEL);
    // 3. attention
    attn_kernel<<<NB * NHEAD, 256>>>(qkv, ao);
    // 4. x = src + ao @ out_w^T + out_b  (TF32)
    tgemm<false><<<dim3(DMODEL / 128, mt_tok, 1), 256, SMEM_BYTES>>>(
        ao, ow, ob, src, x, TOK, DMODEL, DMODEL);
    // 5. LN2 -> fp32 + bf16
    ln_kernel<<<TOK, 256>>>(x, ln2w, ln2b, ffn, ffnb);
    // 6. router top-2 + routing tables
    router_kernel<<<NB, 256>>>(ffn, rw, topi, gates);
    moe_setup<<<1, 256>>>(topi, order, tileE, tileR, tileM, ntiles);
    // 7. MoE layer 1 (gather A, sorted C, bf16 out)
    bgemm<1, true, true><<<dim3(FF / 128, MAXT), 256, BGSMEM>>>(
        ffnb, ew1t, eb1, hmoe, 0, FF, DMODEL, order, tileE, tileR, tileM, ntiles);
    // 8. MoE layer 2 (contiguous A, scatter C to pair-indexed eo, fp32 out)
    bgemm<2, false, false><<<dim3(DMODEL / 128, MAXT), 256, BGSMEM>>>(
        hmoe, ew2t, eb2, eo, 0, DMODEL, FF, order, tileE, tileR, tileM, ntiles);
    // 9. shared layer 1
    bgemm<0, true, true><<<dim3(FF / 128, mt_tok), 256, BGSMEM>>>(
        ffnb, sw1t, sb1, hsh, TOK, FF, DMODEL, nullptr, nullptr, nullptr, nullptr, nullptr);
    // 10. shared layer 2
    bgemm<0, false, false><<<dim3(DMODEL / 128, mt_tok), 256, BGSMEM>>>(
        hsh, sw2t, sb2, sho, TOK, DMODEL, FF, nullptr, nullptr, nullptr, nullptr, nullptr);
    // 11. out = x + moe + shared
    combine_kernel<<<TOK, 256>>>(x, sho, eo, gates, (float*)d_out);
}

// round 8
// speedup vs baseline: 8.1719x; 1.0911x over previous
#include <cuda_runtime.h>
#include <cuda_bf16.h>

// ---------------- problem constants ----------------
#define NB      128
#define SEQ     77
#define DMODEL  1024
#define NHEAD   16
#define FF      4096
#define NEXP    8
#define TOPK    2
#define TOK     (NB * SEQ)          // 9856
#define QKVD    (3 * DMODEL)        // 3072
#define NPAIR   (NB * TOPK)         // 256
#define TOTROWS (NPAIR * SEQ)       // 19712
#define MAXT    162                 // max single-expert M-tiles

typedef __nv_bfloat16 bf16;

// ---------------- scratch (device globals; no allocation) ----------------
__device__ float g_xn  [(size_t)TOK * DMODEL];
__device__ float g_qkv [(size_t)TOK * QKVD];
__device__ float g_ao  [(size_t)TOK * DMODEL];
__device__ float g_x   [(size_t)TOK * DMODEL];
__device__ float g_ffn [(size_t)TOK * DMODEL];
__device__ bf16  g_ffnb[(size_t)TOK * DMODEL];
__device__ bf16  g_hmoe[(size_t)TOTROWS * FF];      // expert-sorted rows
__device__ float g_eo  [(size_t)TOTROWS * DMODEL];  // pair-indexed
__device__ bf16  g_hsh [(size_t)TOK * FF];
__device__ float g_sho [(size_t)TOK * DMODEL];
__device__ int   g_topi [NPAIR];
__device__ float g_gates[NPAIR];
// routing/tiling tables
__device__ int g_order[NPAIR];
__device__ int g_tileE[MAXT];
__device__ int g_tileR[MAXT];
__device__ int g_tileM[MAXT];
__device__ int g_ntiles;
// transposed bf16 weights
__device__ bf16 g_ew1t[(size_t)NEXP * FF * DMODEL];
__device__ bf16 g_ew2t[(size_t)NEXP * DMODEL * FF];
__device__ bf16 g_sw1t[(size_t)FF * DMODEL];
__device__ bf16 g_sw2t[(size_t)DMODEL * FF];
// tf32 pre-rounded fp32 weights
__device__ float g_pwt[(size_t)QKVD * DMODEL];
__device__ float g_owt[(size_t)DMODEL * DMODEL];

// ---------------- helpers ----------------
__device__ __forceinline__ unsigned cvt_tf32(float x) {
    unsigned r;
    asm("cvt.rna.tf32.f32 %0, %1;" : "=r"(r) : "f"(x));
    return r;
}
__device__ __forceinline__ void cp_async16(void* dst, const void* src, int sz) {
    unsigned saddr = (unsigned)__cvta_generic_to_shared(dst);
    asm volatile("cp.async.cg.shared.global [%0], [%1], 16, %2;\n"
                 :: "r"(saddr), "l"(src), "r"(sz));
}
__device__ __forceinline__ void cp_commit() {
    asm volatile("cp.async.commit_group;\n");
}
__device__ __forceinline__ void cp_wait1() {
    asm volatile("cp.async.wait_group 1;\n");
}
__device__ __forceinline__ void ldsm4(unsigned& r0, unsigned& r1,
                                      unsigned& r2, unsigned& r3, unsigned addr) {
    asm volatile("ldmatrix.sync.aligned.m8n8.x4.shared.b16 {%0,%1,%2,%3}, [%4];"
                 : "=r"(r0), "=r"(r1), "=r"(r2), "=r"(r3) : "r"(addr));
}

// ================= bf16 tensor-core GEMM (K-chunk 64, 2-stage) =============
// MODE 0: plain          A rows m0+i,                 C rows m0+i
// MODE 1: MoE layer 1    A rows gathered via order[], C rows sorted (rowbase+i)
// MODE 2: MoE layer 2    A rows sorted (contiguous),  C rows scattered via order[]
// B always pre-transposed bf16 [N][K]; expert weights selected by tile table.
#define AS2   72                    // smem k-pitch in bf16 (144B): ldsm conflict-free
#define TB2   (128 * AS2)           // 9216 bf16 per tile buffer
#define BGSMEM (4 * TB2 * (int)sizeof(bf16))   // 73728 B (2-stage A+B)

template<int MODE, bool RELU, bool OUTBF>
__global__ void __launch_bounds__(256, 2) bgemm(
    const bf16* __restrict__ A, const bf16* __restrict__ Bm,
    const float* __restrict__ bias, void* __restrict__ C,
    int M, int N, int K,
    const int* __restrict__ order, const int* __restrict__ tileE,
    const int* __restrict__ tileR, const int* __restrict__ tileM,
    const int* __restrict__ ntiles)
{
    extern __shared__ bf16 sh[];

    int ty = blockIdx.y;
    int expert = 0, rowbase = 0, Mloc = 128, m0 = 0;
    if (MODE == 0) {
        m0 = ty * 128;
        Mloc = M - m0; if (Mloc > 128) Mloc = 128;
    } else {
        if (ty >= *ntiles) return;
        expert  = tileE[ty];
        rowbase = tileR[ty];
        Mloc    = tileM[ty];
    }
    const bf16* Bp = Bm + (long)expert * N * K;
    const float* biasp = bias ? (bias + (long)expert * N) : nullptr;

    int n0 = blockIdx.x * 128;
    int tid = threadIdx.x, lane = tid & 31, w = tid >> 5;
    int warp_m = (w & 3) * 32;
    int warp_n = (w >> 2) * 64;

    // ---- per-thread load row pointers (16B segments) ----
    int r0 = tid >> 3;              // 0..31
    int c16 = tid & 7;              // 8 segments of 16B across 64 k (128B row)
    int so = c16 * 8;               // bf16 offset within row
    const bf16* arow[4]; int asz[4];
    const bf16* brow[4];
#pragma unroll
    for (int j = 0; j < 4; j++) {
        int i = r0 + j * 32;
        bool valid = i < Mloc;
        asz[j] = valid ? 16 : 0;
        if (MODE == 0) {
            arow[j] = A + (long)(valid ? (m0 + i) : 0) * K;
        } else if (MODE == 1) {
            int r = rowbase + i;
            int rc = r < TOTROWS ? r : TOTROWS - 1;
            int p = order[rc / SEQ];
            int s = rc % SEQ;
            int b = p / TOPK;
            arow[j] = A + ((long)b * SEQ + s) * K;
        } else {
            int r = rowbase + i;
            arow[j] = A + (long)(valid ? r : 0) * K;
        }
        brow[j] = Bp + (long)(n0 + i) * K;
    }

    // ---- ldmatrix per-lane smem byte offsets (within one buffer, kk=0) ----
    unsigned smem_u32 = (unsigned)__cvta_generic_to_shared(sh);
    unsigned aOff[2], bOff[4];
    {
        int la = lane & 15, ha = lane >> 4;            // A: rows, k-half
        int nb = (lane & 7) + ((lane >> 4) & 1) * 8;   // B: n within 16
        int kb = ((lane >> 3) & 1) * 8;                // B: k-half
#pragma unroll
        for (int mi = 0; mi < 2; mi++)
            aOff[mi] = ((warp_m + mi * 16 + la) * AS2 + ha * 8) * 2;
#pragma unroll
        for (int nj = 0; nj < 4; nj++)
            bOff[nj] = ((warp_n + nj * 16 + nb) * AS2 + kb) * 2;
    }

    float c[2][8][4];
#pragma unroll
    for (int i = 0; i < 2; i++)
#pragma unroll
        for (int j = 0; j < 8; j++)
#pragma unroll
            for (int q = 0; q < 4; q++) c[i][j][q] = 0.f;

    const int nChunks = K >> 6;

    auto loadChunk = [&](int k0, int buf) {
        bf16* Ad = sh + buf * TB2;
        bf16* Bd = sh + (2 + buf) * TB2;
#pragma unroll
        for (int j = 0; j < 4; j++) {
            int i = r0 + j * 32;
            cp_async16(Ad + i * AS2 + so, arow[j] + k0 + so, asz[j]);
            cp_async16(Bd + i * AS2 + so, brow[j] + k0 + so, 16);
        }
    };

    loadChunk(0, 0);
    cp_commit();

    for (int ch = 0; ch < nChunks; ch++) {
        if (ch + 1 < nChunks) loadChunk((ch + 1) << 6, (ch + 1) & 1);
        cp_commit();
        cp_wait1();
        __syncthreads();

        int buf = ch & 1;
        unsigned Abase = smem_u32 + buf * (TB2 * 2);
        unsigned Bbase = smem_u32 + (2 + buf) * (TB2 * 2);

#pragma unroll
        for (int kk = 0; kk < 64; kk += 16) {
            unsigned kByte = kk * 2;
            unsigned a[2][4];
#pragma unroll
            for (int mi = 0; mi < 2; mi++)
                ldsm4(a[mi][0], a[mi][1], a[mi][2], a[mi][3],
                      Abase + aOff[mi] + kByte);
#pragma unroll
            for (int nj = 0; nj < 4; nj++) {
                unsigned b0, b1, b2, b3;
                ldsm4(b0, b1, b2, b3, Bbase + bOff[nj] + kByte);
#pragma unroll
                for (int mi = 0; mi < 2; mi++) {
                    asm volatile(
                        "mma.sync.aligned.m16n8k16.row.col.f32.bf16.bf16.f32 "
                        "{%0,%1,%2,%3},{%4,%5,%6,%7},{%8,%9},{%0,%1,%2,%3};"
                        : "+f"(c[mi][nj * 2][0]), "+f"(c[mi][nj * 2][1]),
                          "+f"(c[mi][nj * 2][2]), "+f"(c[mi][nj * 2][3])
                        : "r"(a[mi][0]), "r"(a[mi][1]), "r"(a[mi][2]), "r"(a[mi][3]),
                          "r"(b0), "r"(b1));
                    asm volatile(
                        "mma.sync.aligned.m16n8k16.row.col.f32.bf16.bf16.f32 "
                        "{%0,%1,%2,%3},{%4,%5,%6,%7},{%8,%9},{%0,%1,%2,%3};"
                        : "+f"(c[mi][nj * 2 + 1][0]), "+f"(c[mi][nj * 2 + 1][1]),
                          "+f"(c[mi][nj * 2 + 1][2]), "+f"(c[mi][nj * 2 + 1][3])
                        : "r"(a[mi][0]), "r"(a[mi][1]), "r"(a[mi][2]), "r"(a[mi][3]),
                          "r"(b2), "r"(b3));
                }
            }
        }
        __syncthreads();
    }

    // -------- epilogue --------
#pragma unroll
    for (int mi = 0; mi < 2; mi++) {
#pragma unroll
        for (int half = 0; half < 2; half++) {
            int li = warp_m + mi * 16 + (lane >> 2) + half * 8;
            if (li < Mloc) {
                long ro;
                if (MODE == 0) {
                    ro = (long)(m0 + li) * N;
                } else if (MODE == 1) {
                    ro = (long)(rowbase + li) * N;
                } else {
                    int r = rowbase + li;
                    int p = order[r / SEQ];
                    int s = r % SEQ;
                    ro = ((long)p * SEQ + s) * N;
                }
#pragma unroll
                for (int ni = 0; ni < 8; ni++) {
                    int col = n0 + warp_n + ni * 8 + (lane & 3) * 2;
                    float v0 = c[mi][ni][half * 2 + 0];
                    float v1 = c[mi][ni][half * 2 + 1];
                    if (biasp) { v0 += biasp[col]; v1 += biasp[col + 1]; }
                    if (RELU)  { v0 = fmaxf(v0, 0.f); v1 = fmaxf(v1, 0.f); }
                    if (OUTBF) {
                        __nv_bfloat162 pk = __float22bfloat162_rn(make_float2(v0, v1));
                        *(__nv_bfloat162*)((bf16*)C + ro + col) = pk;
                    } else {
                        *(float2*)((float*)C + ro + col) = make_float2(v0, v1);
                    }
                }
            }
        }
    }
}

// ================= TF32 GEMM (pre-rounded operands; B row-major [N,K]) =====
#define ASTRIDE   36
#define ABUF (128 * ASTRIDE)
#define SMEM_BYTES  (4 * ABUF * 4)    // 73728

template<bool RELU>
__global__ void __launch_bounds__(256, 2) tgemm(
    const float* __restrict__ A, const float* __restrict__ Bm,
    const float* __restrict__ bias, const float* __restrict__ resid,
    float* __restrict__ C, int M, int N, int K)
{
    extern __shared__ float sm[];
    float* As = sm;
    float* Bs = sm + 2 * ABUF;

    int m0 = blockIdx.y * 128;
    int n0 = blockIdx.x * 128;
    int tid = threadIdx.x, lane = tid & 31, w = tid >> 5;
    int warp_m = (w & 3) * 32;
    int warp_n = (w >> 2) * 64;

    float c[2][8][4];
#pragma unroll
    for (int i = 0; i < 2; i++)
#pragma unroll
        for (int j = 0; j < 8; j++)
#pragma unroll
            for (int q = 0; q < 4; q++) c[i][j][q] = 0.f;

    const int nChunks = K >> 5;

    auto copyA = [&](int k0, int buf) {
        float* dst = As + buf * ABUF;
#pragma unroll
        for (int i = 0; i < 4; i++) {
            int f = tid + i * 256;
            int row = f >> 3;
            int kq  = (f & 7) * 4;
            int gr = m0 + row;
            int sz = (gr < M) ? 16 : 0;
            const float* src = A + (long)(gr < M ? gr : 0) * K + k0 + kq;
            cp_async16(dst + row * ASTRIDE + kq, src, sz);
        }
    };
    auto copyB = [&](int k0, int buf) {
        float* dst = Bs + buf * ABUF;
#pragma unroll
        for (int i = 0; i < 4; i++) {
            int f = tid + i * 256;
            int row = f >> 3;
            int kq  = (f & 7) * 4;
            const float* src = Bm + (long)(n0 + row) * K + k0 + kq;
            cp_async16(dst + row * ASTRIDE + kq, src, 16);
        }
    };

    copyA(0, 0); copyB(0, 0);
    cp_commit();

    for (int ch = 0; ch < nChunks; ch++) {
        if (ch + 1 < nChunks) {
            copyA((ch + 1) << 5, (ch + 1) & 1);
            copyB((ch + 1) << 5, (ch + 1) & 1);
        }
        cp_commit();
        cp_wait1();
        __syncthreads();

        const unsigned* Ab = (const unsigned*)(As + (ch & 1) * ABUF);
        const unsigned* Bb = (const unsigned*)(Bs + (ch & 1) * ABUF);

#pragma unroll
        for (int kk = 0; kk < 32; kk += 8) {
            int kb = kk + (lane & 3);
            unsigned a[2][4];
#pragma unroll
            for (int mi = 0; mi < 2; mi++) {
                int r = warp_m + mi * 16 + (lane >> 2);
                a[mi][0] = Ab[r * ASTRIDE + kb];
                a[mi][1] = Ab[(r + 8) * ASTRIDE + kb];
                a[mi][2] = Ab[r * ASTRIDE + kb + 4];
                a[mi][3] = Ab[(r + 8) * ASTRIDE + kb + 4];
            }
#pragma unroll
            for (int ni = 0; ni < 8; ni++) {
                int n = warp_n + ni * 8 + (lane >> 2);
                unsigned b0 = Bb[n * ASTRIDE + kb];
                unsigned b1 = Bb[n * ASTRIDE + kb + 4];
#pragma unroll
                for (int mi = 0; mi < 2; mi++) {
                    asm volatile(
                        "mma.sync.aligned.m16n8k8.row.col.f32.tf32.tf32.f32 "
                        "{%0,%1,%2,%3},{%4,%5,%6,%7},{%8,%9},{%0,%1,%2,%3};"
                        : "+f"(c[mi][ni][0]), "+f"(c[mi][ni][1]),
                          "+f"(c[mi][ni][2]), "+f"(c[mi][ni][3])
                        : "r"(a[mi][0]), "r"(a[mi][1]), "r"(a[mi][2]), "r"(a[mi][3]),
                          "r"(b0), "r"(b1));
                }
            }
        }
        __syncthreads();
    }

#pragma unroll
    for (int mi = 0; mi < 2; mi++) {
#pragma unroll
        for (int half = 0; half < 2; half++) {
            int row = m0 + warp_m + mi * 16 + (lane >> 2) + half * 8;
            if (row < M) {
                long ro = (long)row * N;
#pragma unroll
                for (int ni = 0; ni < 8; ni++) {
                    int col = n0 + warp_n + ni * 8 + (lane & 3) * 2;
                    float v0 = c[mi][ni][half * 2 + 0];
                    float v1 = c[mi][ni][half * 2 + 1];
                    if (bias)  { v0 += bias[col]; v1 += bias[col + 1]; }
                    if (RELU)  { v0 = fmaxf(v0, 0.f); v1 = fmaxf(v1, 0.f); }
                    if (resid) { v0 += resid[ro + col]; v1 += resid[ro + col + 1]; }
                    *(float2*)(C + ro + col) = make_float2(v0, v1);
                }
            }
        }
    }
}

// ---------------- tf32 pre-round (fp32 -> nearest tf32, stored fp32) -------
__global__ __launch_bounds__(256) void round_tf32_kernel(
    const float* __restrict__ in, float* __restrict__ out, long n)
{
    long i = (long)blockIdx.x * 1024 + threadIdx.x * 4;
    if (i + 3 < n) {
        float4 v = *(const float4*)(in + i);
        v.x = __uint_as_float(cvt_tf32(v.x));
        v.y = __uint_as_float(cvt_tf32(v.y));
        v.z = __uint_as_float(cvt_tf32(v.z));
        v.w = __uint_as_float(cvt_tf32(v.w));
        *(float4*)(out + i) = v;
    }
}

// ---------------- transpose + convert fp32 [R,C] -> bf16 [C,R] -------------
__global__ __launch_bounds__(256) void tconv_kernel(
    const float* __restrict__ in, bf16* __restrict__ out, int R, int C)
{
    __shared__ float tile[32][33];
    long zoff = (long)blockIdx.z * R * C;
    in += zoff; out += zoff;
    int tx = threadIdx.x & 31, ty = threadIdx.x >> 5;
    int c0 = blockIdx.x * 32, r0 = blockIdx.y * 32;
#pragma unroll
    for (int j = 0; j < 4; j++)
        tile[ty + j * 8][tx] = in[(long)(r0 + ty + j * 8) * C + c0 + tx];
    __syncthreads();
#pragma unroll
    for (int j = 0; j < 4; j++)
        out[(long)(c0 + ty + j * 8) * R + r0 + tx] =
            __float2bfloat16_rn(tile[tx][ty + j * 8]);
}

// ---------------- layernorm (optional tf32-rounding / bf16 output) ---------
__global__ __launch_bounds__(256) void ln_kernel(
    const float* __restrict__ x, const float* __restrict__ w,
    const float* __restrict__ bvec, float* __restrict__ y,
    bf16* __restrict__ yb, int round32)
{
    long t = blockIdx.x;
    const float* xr = x + t * DMODEL;
    float* yr = y + t * DMODEL;
    int tid = threadIdx.x;
    float v[4];
    float s = 0.f, s2 = 0.f;
#pragma unroll
    for (int i = 0; i < 4; i++) {
        v[i] = xr[tid + i * 256];
        s += v[i]; s2 += v[i] * v[i];
    }
#pragma unroll
    for (int o = 16; o; o >>= 1) {
        s  += __shfl_xor_sync(0xffffffffu, s, o);
        s2 += __shfl_xor_sync(0xffffffffu, s2, o);
    }
    __shared__ float rs[8], rs2[8];
    if ((tid & 31) == 0) { rs[tid >> 5] = s; rs2[tid >> 5] = s2; }
    __syncthreads();
    float ts = 0.f, ts2 = 0.f;
#pragma unroll
    for (int i = 0; i < 8; i++) { ts += rs[i]; ts2 += rs2[i]; }
    float mean = ts * (1.0f / DMODEL);
    float var  = ts2 * (1.0f / DMODEL) - mean * mean;
    float inv  = rsqrtf(var + 1e-5f);
#pragma unroll
    for (int i = 0; i < 4; i++) {
        int d = tid + i * 256;
        float o = (v[i] - mean) * inv * w[d] + bvec[d];
        yr[d] = round32 ? __uint_as_float(cvt_tf32(o)) : o;
        if (yb) yb[t * DMODEL + d] = __float2bfloat16_rn(o);
    }
}

// ---------------- fused attention (one block per (b,h)) -------------------
// Output pre-rounded to tf32 (consumed only by tgemm out-proj).
__global__ __launch_bounds__(256) void attn_kernel(
    const float* __restrict__ qkv, float* __restrict__ ao)
{
    __shared__ float Ks[SEQ * 65];
    __shared__ float Vs[SEQ * 65];
    __shared__ float qb[8][64];
    __shared__ float pb[8][80];

    int bh = blockIdx.x;
    int b = bh >> 4, h = bh & 15;
    int tid = threadIdx.x, lane = tid & 31, wrp = tid >> 5;
    long tok0 = (long)b * SEQ;

    for (int idx = tid; idx < SEQ * 64; idx += 256) {
        int s = idx >> 6, d = idx & 63;
        long off = (tok0 + s) * QKVD + h * 64 + d;
        Ks[s * 65 + d] = qkv[off + DMODEL];
        Vs[s * 65 + d] = qkv[off + 2 * DMODEL];
    }
    __syncthreads();

    for (int s = wrp; s < SEQ; s += 8) {
        long qoff = (tok0 + s) * QKVD + h * 64;
        qb[wrp][lane]      = qkv[qoff + lane];
        qb[wrp][lane + 32] = qkv[qoff + lane + 32];
        __syncwarp();

        float e[3];
        float mx = -1e30f;
#pragma unroll
        for (int jj = 0; jj < 3; jj++) {
            int j = lane + jj * 32;
            float dot = -1e30f;
            if (j < SEQ) {
                const float* kr = Ks + j * 65;
                float a = 0.f;
#pragma unroll
                for (int d = 0; d < 64; d++) a += qb[wrp][d] * kr[d];
                dot = a * 0.125f;
            }
            e[jj] = dot;
            mx = fmaxf(mx, dot);
        }
#pragma unroll
        for (int o = 16; o; o >>= 1) mx = fmaxf(mx, __shfl_xor_sync(0xffffffffu, mx, o));

        float ssum = 0.f;
#pragma unroll
        for (int jj = 0; jj < 3; jj++) {
            int j = lane + jj * 32;
            float p = (j < SEQ) ? __expf(e[jj] - mx) : 0.f;
            e[jj] = p; ssum += p;
        }
#pragma unroll
        for (int o = 16; o; o >>= 1) ssum += __shfl_xor_sync(0xffffffffu, ssum, o);
        float inv = 1.0f / ssum;
#pragma unroll
        for (int jj = 0; jj < 3; jj++) {
            int j = lane + jj * 32;
            if (j < SEQ) pb[wrp][j] = e[jj] * inv;
        }
        __syncwarp();

        float a0 = 0.f, a1 = 0.f;
        for (int j = 0; j < SEQ; j++) {
            float p = pb[wrp][j];
            a0 += p * Vs[j * 65 + lane];
            a1 += p * Vs[j * 65 + lane + 32];
        }
        long orow = (tok0 + s) * DMODEL + h * 64;
        ao[orow + lane]      = __uint_as_float(cvt_tf32(a0));
        ao[orow + lane + 32] = __uint_as_float(cvt_tf32(a1));
        __syncwarp();
    }
}

// ---------------- router ----------------
__global__ __launch_bounds__(256) void router_kernel(
    const float* __restrict__ ffn, const float* __restrict__ rw,
    int* __restrict__ topi, float* __restrict__ gates)
{
    int b = blockIdx.x;
    const float* xr = ffn + (long)b * SEQ * DMODEL;
    int tid = threadIdx.x;
    int e = tid >> 5, lane = tid & 31;
    const float* wr = rw + e * DMODEL;
    float s = 0.f;
    for (int d = lane; d < DMODEL; d += 32) s += xr[d] * wr[d];
#pragma unroll
    for (int o = 16; o; o >>= 1) s += __shfl_xor_sync(0xffffffffu, s, o);
    __shared__ float lg[NEXP];
    if (lane == 0) lg[e] = s;
    __syncthreads();
    if (tid == 0) {
        int i0 = 0; float v0 = lg[0];
        for (int i = 1; i < NEXP; i++) if (lg[i] > v0) { v0 = lg[i]; i0 = i; }
        int i1 = -1; float v1 = -1e30f;
        for (int i = 0; i < NEXP; i++) if (i != i0 && lg[i] > v1) { v1 = lg[i]; i1 = i; }
        float e1 = __expf(v1 - v0);
        float den = 1.f + e1;
        topi[b * TOPK]     = i0;
        topi[b * TOPK + 1] = i1;
        gates[b * TOPK]     = 1.f / den;
        gates[b * TOPK + 1] = e1 / den;
    }
}

// ---------------- MoE routing setup ----------------
__global__ void moe_setup(const int* __restrict__ topi,
                          int* __restrict__ order, int* __restrict__ tileE,
                          int* __restrict__ tileR, int* __restrict__ tileM,
                          int* __restrict__ ntiles)
{
    __shared__ int cnt[NEXP], off[NEXP];
    int tid = threadIdx.x;
    if (tid < NEXP) cnt[tid] = 0;
    __syncthreads();
    int e = topi[tid];
    int pos = atomicAdd(&cnt[e], 1);
    __syncthreads();
    if (tid == 0) {
        int o = 0;
        for (int i = 0; i < NEXP; i++) { off[i] = o; o += cnt[i]; }
    }
    __syncthreads();
    order[off[e] + pos] = tid;
    if (tid == 0) {
        int t = 0, rowbase = 0;
        for (int e2 = 0; e2 < NEXP; e2++) {
            int rows = cnt[e2] * SEQ;
            int done = 0;
            while (done < rows) {
                int m = rows - done; if (m > 128) m = 128;
                tileE[t] = e2; tileR[t] = rowbase + done; tileM[t] = m;
                t++; done += 128;
            }
            rowbase += rows;
        }
        *ntiles = t;
    }
}

// ---------------- final combine ----------------
__global__ __launch_bounds__(256) void combine_kernel(
    const float* __restrict__ x, const float* __restrict__ sho,
    const float* __restrict__ eo, const float* __restrict__ gates,
    float* __restrict__ out)
{
    long t = blockIdx.x;
    int tid = threadIdx.x;
    int b = (int)(t / SEQ);
    int s = (int)(t - (long)b * SEQ);
    float g0 = gates[b * TOPK], g1 = gates[b * TOPK + 1];
    long base = t * DMODEL;
    long e0 = ((long)(b * TOPK) * SEQ + s) * DMODEL;
    long e1 = e0 + (long)SEQ * DMODEL;
#pragma unroll
    for (int i = 0; i < 4; i++) {
        int d = tid + i * 256;
        out[base + d] = x[base + d] + sho[base + d] + g0 * eo[e0 + d] + g1 * eo[e1 + d];
    }
}

// ---------------- launch ----------------
extern "C" void kernel_launch(void* const* d_in, const int* in_sizes, int n_in,
                              void* d_out, int out_size)
{
    const float* src   = (const float*)d_in[0];
    const float* pw    = (const float*)d_in[1];
    const float* pbias = (const float*)d_in[2];
    const float* ow    = (const float*)d_in[3];
    const float* ob    = (const float*)d_in[4];
    const float* ln1w  = (const float*)d_in[5];
    const float* ln1b  = (const float*)d_in[6];
    const float* ln2w  = (const float*)d_in[7];
    const float* ln2b  = (const float*)d_in[8];
    const float* rw    = (const float*)d_in[9];
    const float* ew1   = (const float*)d_in[10];
    const float* eb1   = (const float*)d_in[11];
    const float* ew2   = (const float*)d_in[12];
    const float* eb2   = (const float*)d_in[13];
    const float* sw1   = (const float*)d_in[14];
    const float* sb1   = (const float*)d_in[15];
    const float* sw2   = (const float*)d_in[16];
    const float* sb2   = (const float*)d_in[17];

    float *xn, *qkv, *ao, *x, *ffn, *eo, *sho, *gates, *pwt, *owt;
    bf16 *ffnb, *hmoe, *hsh, *ew1t, *ew2t, *sw1t, *sw2t;
    int *topi, *order, *tileE, *tileR, *tileM, *ntiles;
    cudaGetSymbolAddress((void**)&xn,   g_xn);
    cudaGetSymbolAddress((void**)&qkv,  g_qkv);
    cudaGetSymbolAddress((void**)&ao,   g_ao);
    cudaGetSymbolAddress((void**)&x,    g_x);
    cudaGetSymbolAddress((void**)&ffn,  g_ffn);
    cudaGetSymbolAddress((void**)&ffnb, g_ffnb);
    cudaGetSymbolAddress((void**)&hmoe, g_hmoe);
    cudaGetSymbolAddress((void**)&eo,   g_eo);
    cudaGetSymbolAddress((void**)&hsh,  g_hsh);
    cudaGetSymbolAddress((void**)&sho,  g_sho);
    cudaGetSymbolAddress((void**)&topi, g_topi);
    cudaGetSymbolAddress((void**)&gates,g_gates);
    cudaGetSymbolAddress((void**)&order,g_order);
    cudaGetSymbolAddress((void**)&tileE,g_tileE);
    cudaGetSymbolAddress((void**)&tileR,g_tileR);
    cudaGetSymbolAddress((void**)&tileM,g_tileM);
    cudaGetSymbolAddress((void**)&ntiles,g_ntiles);
    cudaGetSymbolAddress((void**)&ew1t, g_ew1t);
    cudaGetSymbolAddress((void**)&ew2t, g_ew2t);
    cudaGetSymbolAddress((void**)&sw1t, g_sw1t);
    cudaGetSymbolAddress((void**)&sw2t, g_sw2t);
    cudaGetSymbolAddress((void**)&pwt,  g_pwt);
    cudaGetSymbolAddress((void**)&owt,  g_owt);

    cudaFuncSetAttribute(tgemm<false>, cudaFuncAttributeMaxDynamicSharedMemorySize, SMEM_BYTES);
    cudaFuncSetAttribute(bgemm<0, true,  true >, cudaFuncAttributeMaxDynamicSharedMemorySize, BGSMEM);
    cudaFuncSetAttribute(bgemm<0, false, false>, cudaFuncAttributeMaxDynamicSharedMemorySize, BGSMEM);
    cudaFuncSetAttribute(bgemm<1, true,  true >, cudaFuncAttributeMaxDynamicSharedMemorySize, BGSMEM);
    cudaFuncSetAttribute(bgemm<2, false, false>, cudaFuncAttributeMaxDynamicSharedMemorySize, BGSMEM);

    const int mt_tok = TOK / 128;   // 77 (exact)

    // 0. weight convert/round prep
    tconv_kernel<<<dim3(FF / 32, DMODEL / 32, NEXP), 256>>>(ew1, ew1t, DMODEL, FF);
    tconv_kernel<<<dim3(DMODEL / 32, FF / 32, NEXP), 256>>>(ew2, ew2t, FF, DMODEL);
    tconv_kernel<<<dim3(FF / 32, DMODEL / 32, 1),    256>>>(sw1, sw1t, DMODEL, FF);
    tconv_kernel<<<dim3(DMODEL / 32, FF / 32, 1),    256>>>(sw2, sw2t, FF, DMODEL);
    round_tf32_kernel<<<(QKVD * DMODEL) / 1024, 256>>>(pw, pwt, (long)QKVD * DMODEL);
    round_tf32_kernel<<<(DMODEL * DMODEL) / 1024, 256>>>(ow, owt, (long)DMODEL * DMODEL);

    // 1. LN1 -> tf32-rounded xn
    ln_kernel<<<TOK, 256>>>(src, ln1w, ln1b, xn, nullptr, 1);
    // 2. QKV (TF32, pre-rounded operands)
    tgemm<false><<<dim3(QKVD / 128, mt_tok, 1), 256, SMEM_BYTES>>>(
        xn, pwt, pbias, nullptr, qkv, TOK, QKVD, DMODEL);
    // 3. attention (writes tf32-rounded ao)
    attn_kernel<<<NB * NHEAD, 256>>>(qkv, ao);
    // 4. x = src + ao @ out_w^T + out_b  (TF32, pre-rounded operands)
    tgemm<false><<<dim3(DMODEL / 128, mt_tok, 1), 256, SMEM_BYTES>>>(
        ao, owt, ob, src, x, TOK, DMODEL, DMODEL);
    // 5. LN2 -> fp32 (router) + bf16 (GEMM A)
    ln_kernel<<<TOK, 256>>>(x, ln2w, ln2b, ffn, ffnb, 0);
    // 6. router top-2 + routing tables
    router_kernel<<<NB, 256>>>(ffn, rw, topi, gates);
    moe_setup<<<1, 256>>>(topi, order, tileE, tileR, tileM, ntiles);
    // 7. MoE layer 1 (gather A, sorted C, bf16 out)
    bgemm<1, true, true><<<dim3(FF / 128, MAXT), 256, BGSMEM>>>(
        ffnb, ew1t, eb1, hmoe, 0, FF, DMODEL, order, tileE, tileR, tileM, ntiles);
    // 8. MoE layer 2 (contiguous A, scatter C, fp32 out)
    bgemm<2, false, false><<<dim3(DMODEL / 128, MAXT), 256, BGSMEM>>>(
        hmoe, ew2t, eb2, eo, 0, DMODEL, FF, order, tileE, tileR, tileM, ntiles);
    // 9. shared layer 1
    bgemm<0, true, true><<<dim3(FF / 128, mt_tok), 256, BGSMEM>>>(
        ffnb, sw1t, sb1, hsh, TOK, FF, DMODEL, nullptr, nullptr, nullptr, nullptr, nullptr);
    // 10. shared layer 2
    bgemm<0, false, false><<<dim3(DMODEL / 128, mt_tok), 256, BGSMEM>>>(
        hsh, sw2t, sb2, sho, TOK, DMODEL, FF, nullptr, nullptr, nullptr, nullptr, nullptr);
    // 11. out = x + moe + shared
    combine_kernel<<<TOK, 256>>>(x, sho, eo, gates, (float*)d_out);
}